// round 1
// baseline (speedup 1.0000x reference)
#include <cuda_runtime.h>
#include <cuda_bf16.h>
#include <cstdint>

// Problem constants
#define BB 2
#define SS 2048
#define DD 1024
#define HH 16
#define HD 64
#define MM (BB * SS)          // 4096 rows
#define ATTN_SCALE 0.125f     // 1/sqrt(64)

// ---------------------------------------------------------------------------
// Scratch (device globals; no runtime allocation allowed)
// ---------------------------------------------------------------------------
__device__ float g_qp[MM * DD];
__device__ float g_kp[MM * DD];
__device__ float g_vp[MM * DD];
__device__ float g_att[MM * DD];

// ---------------------------------------------------------------------------
// SGEMM (NT): C[M,N] = A[M,K] @ W[N,K]^T + bias[N]
// 128x128 tile, BK=8, 256 threads, 8x8 frag per thread, global prefetch.
// M,N,K all multiples of tile sizes for this problem (4096/1024/1024).
// ---------------------------------------------------------------------------
__global__ __launch_bounds__(256, 2)
void sgemm_nt_bias(const float* __restrict__ A, const float* __restrict__ W,
                   const float* __restrict__ bias, float* __restrict__ C,
                   int M, int N, int K)
{
    __shared__ float As[8][128];
    __shared__ float Bs[8][128];

    const int tid = threadIdx.x;
    const int tx = tid & 15;        // 0..15 -> N
    const int ty = tid >> 4;        // 0..15 -> M
    const int m0 = blockIdx.y << 7;
    const int n0 = blockIdx.x << 7;

    const int lr = tid >> 1;        // 0..127
    const int lc = (tid & 1) << 2;  // 0 or 4

    const float* Ag = A + (size_t)(m0 + lr) * K + lc;
    const float* Bg = W + (size_t)(n0 + lr) * K + lc;

    float4 a_next = *(const float4*)(Ag);
    float4 b_next = *(const float4*)(Bg);

    float acc[8][8];
#pragma unroll
    for (int i = 0; i < 8; i++)
#pragma unroll
        for (int j = 0; j < 8; j++) acc[i][j] = 0.f;

    for (int k0 = 0; k0 < K; k0 += 8) {
        __syncthreads();
        As[lc + 0][lr] = a_next.x;
        As[lc + 1][lr] = a_next.y;
        As[lc + 2][lr] = a_next.z;
        As[lc + 3][lr] = a_next.w;
        Bs[lc + 0][lr] = b_next.x;
        Bs[lc + 1][lr] = b_next.y;
        Bs[lc + 2][lr] = b_next.z;
        Bs[lc + 3][lr] = b_next.w;
        __syncthreads();

        if (k0 + 8 < K) {               // prefetch next K-slab
            a_next = *(const float4*)(Ag + k0 + 8);
            b_next = *(const float4*)(Bg + k0 + 8);
        }

#pragma unroll
        for (int kk = 0; kk < 8; kk++) {
            float4 a0 = *(const float4*)&As[kk][ty * 8];
            float4 a1 = *(const float4*)&As[kk][ty * 8 + 4];
            float4 b0 = *(const float4*)&Bs[kk][tx * 8];
            float4 b1 = *(const float4*)&Bs[kk][tx * 8 + 4];
            float ar[8] = {a0.x, a0.y, a0.z, a0.w, a1.x, a1.y, a1.z, a1.w};
            float br[8] = {b0.x, b0.y, b0.z, b0.w, b1.x, b1.y, b1.z, b1.w};
#pragma unroll
            for (int i = 0; i < 8; i++)
#pragma unroll
                for (int j = 0; j < 8; j++)
                    acc[i][j] += ar[i] * br[j];
        }
    }

    float bb[8];
#pragma unroll
    for (int j = 0; j < 8; j++) bb[j] = bias[n0 + tx * 8 + j];

#pragma unroll
    for (int i = 0; i < 8; i++) {
        size_t row = (size_t)(m0 + ty * 8 + i);
        float* Cp = C + row * N + n0 + tx * 8;
        float4 o0, o1;
        o0.x = acc[i][0] + bb[0]; o0.y = acc[i][1] + bb[1];
        o0.z = acc[i][2] + bb[2]; o0.w = acc[i][3] + bb[3];
        o1.x = acc[i][4] + bb[4]; o1.y = acc[i][5] + bb[5];
        o1.z = acc[i][6] + bb[6]; o1.w = acc[i][7] + bb[7];
        *(float4*)(Cp)     = o0;
        *(float4*)(Cp + 4) = o1;
    }
}

// ---------------------------------------------------------------------------
// Flash attention (fp32, online softmax).
// Grid: (S/128, H, B). Block: 256 threads (16x16), frag 8 rows x 4 cols.
// Q pre-scaled by ATTN_SCALE at load. Layouts [B,S,H*HD] row-major (== [B,S,D]).
// Dynamic smem: Qt[64][132] (d-major), Kt[64][68] (d-major),
//               Vs[64][68] (j-major), Pt[64][132] (j-major) = 100 KB.
// ---------------------------------------------------------------------------
#define QT_STRIDE 132
#define KT_STRIDE 68
#define VS_STRIDE 68
#define PT_STRIDE 132
#define FLASH_SMEM_BYTES ((64 * QT_STRIDE + 64 * KT_STRIDE + 64 * VS_STRIDE + 64 * PT_STRIDE) * 4)

__global__ __launch_bounds__(256, 2)
void flash_attn(const float* __restrict__ Q, const float* __restrict__ K,
                const float* __restrict__ V, float* __restrict__ O)
{
    extern __shared__ float sm[];
    float* Qt = sm;                        // [64][132]  Qt[d][i], pre-scaled
    float* Kt = Qt + 64 * QT_STRIDE;       // [64][68]   Kt[d][j]
    float* Vs = Kt + 64 * KT_STRIDE;       // [64][68]   Vs[j][d]
    float* Pt = Vs + 64 * VS_STRIDE;       // [64][132]  Pt[j][i]

    const int tid = threadIdx.x;
    const int tx = tid & 15;   // 0..15 -> key cols (4 each)
    const int ty = tid >> 4;   // 0..15 -> query rows (8 each)
    const int q0 = blockIdx.x << 7;  // 128 q rows per block
    const int h  = blockIdx.y;
    const int b  = blockIdx.z;

    const float* Qb = Q + ((size_t)(b * SS + q0)) * DD + h * HD;
    const float* Kb = K + ((size_t)b * SS) * DD + h * HD;
    const float* Vb = V + ((size_t)b * SS) * DD + h * HD;

    // Load Q tile [128 x 64], transpose to Qt[d][i], fold in softmax scale.
#pragma unroll
    for (int p = 0; p < 8; p++) {
        int idx = tid + p * 256;
        int r = idx >> 4;            // 0..127
        int c4 = (idx & 15) << 2;    // 0..60
        float4 v4 = *(const float4*)(Qb + (size_t)r * DD + c4);
        Qt[(c4 + 0) * QT_STRIDE + r] = v4.x * ATTN_SCALE;
        Qt[(c4 + 1) * QT_STRIDE + r] = v4.y * ATTN_SCALE;
        Qt[(c4 + 2) * QT_STRIDE + r] = v4.z * ATTN_SCALE;
        Qt[(c4 + 3) * QT_STRIDE + r] = v4.w * ATTN_SCALE;
    }

    float acc[8][4];
    float m_i[8], l_i[8];
#pragma unroll
    for (int i = 0; i < 8; i++) {
        m_i[i] = -__int_as_float(0x7f800000);  // -inf
        l_i[i] = 0.f;
#pragma unroll
        for (int j = 0; j < 4; j++) acc[i][j] = 0.f;
    }

    for (int j0 = 0; j0 < SS; j0 += 64) {
        __syncthreads();  // prev PV done with Vs/Pt; Qt ready on first iter

        // Load K tile transposed, V tile natural
#pragma unroll
        for (int p = 0; p < 4; p++) {
            int idx = tid + p * 256;
            int r = idx >> 4;            // 0..63
            int c4 = (idx & 15) << 2;    // 0..60
            float4 kv = *(const float4*)(Kb + (size_t)(j0 + r) * DD + c4);
            Kt[(c4 + 0) * KT_STRIDE + r] = kv.x;
            Kt[(c4 + 1) * KT_STRIDE + r] = kv.y;
            Kt[(c4 + 2) * KT_STRIDE + r] = kv.z;
            Kt[(c4 + 3) * KT_STRIDE + r] = kv.w;
            float4 vv = *(const float4*)(Vb + (size_t)(j0 + r) * DD + c4);
            *(float4*)(Vs + r * VS_STRIDE + c4) = vv;
        }
        __syncthreads();

        // S = (Q*scale) K^T  -> frag s[8][4]
        float s[8][4];
#pragma unroll
        for (int i = 0; i < 8; i++)
#pragma unroll
            for (int j = 0; j < 4; j++) s[i][j] = 0.f;

#pragma unroll 8
        for (int d = 0; d < 64; d++) {
            float4 a0 = *(const float4*)(Qt + d * QT_STRIDE + ty * 8);
            float4 a1 = *(const float4*)(Qt + d * QT_STRIDE + ty * 8 + 4);
            float4 kk = *(const float4*)(Kt + d * KT_STRIDE + tx * 4);
            float qr[8] = {a0.x, a0.y, a0.z, a0.w, a1.x, a1.y, a1.z, a1.w};
            float kr[4] = {kk.x, kk.y, kk.z, kk.w};
#pragma unroll
            for (int i = 0; i < 8; i++)
#pragma unroll
                for (int j = 0; j < 4; j++)
                    s[i][j] += qr[i] * kr[j];
        }

        // Online softmax per row (16-lane reduction across tx)
#pragma unroll
        for (int i = 0; i < 8; i++) {
            float v = fmaxf(fmaxf(s[i][0], s[i][1]), fmaxf(s[i][2], s[i][3]));
#pragma unroll
            for (int off = 8; off; off >>= 1)
                v = fmaxf(v, __shfl_xor_sync(0xffffffffu, v, off));
            float mnew = fmaxf(m_i[i], v);
            float corr = __expf(m_i[i] - mnew);
            l_i[i] *= corr;
#pragma unroll
            for (int j = 0; j < 4; j++) acc[i][j] *= corr;
            float rs = 0.f;
#pragma unroll
            for (int j = 0; j < 4; j++) {
                s[i][j] = __expf(s[i][j] - mnew);
                rs += s[i][j];
            }
#pragma unroll
            for (int off = 8; off; off >>= 1)
                rs += __shfl_xor_sync(0xffffffffu, rs, off);
            l_i[i] += rs;
            m_i[i] = mnew;
            // store P transposed: Pt[j][i]
#pragma unroll
            for (int j = 0; j < 4; j++)
                Pt[(tx * 4 + j) * PT_STRIDE + ty * 8 + i] = s[i][j];
        }
        __syncthreads();

        // O += P V
#pragma unroll 8
        for (int jj = 0; jj < 64; jj++) {
            float4 p0 = *(const float4*)(Pt + jj * PT_STRIDE + ty * 8);
            float4 p1 = *(const float4*)(Pt + jj * PT_STRIDE + ty * 8 + 4);
            float4 vv = *(const float4*)(Vs + jj * VS_STRIDE + tx * 4);
            float pr[8] = {p0.x, p0.y, p0.z, p0.w, p1.x, p1.y, p1.z, p1.w};
            float vr[4] = {vv.x, vv.y, vv.z, vv.w};
#pragma unroll
            for (int i = 0; i < 8; i++)
#pragma unroll
                for (int j = 0; j < 4; j++)
                    acc[i][j] += pr[i] * vr[j];
        }
    }

    // Epilogue: normalize and write [B,S,D]
#pragma unroll
    for (int i = 0; i < 8; i++) {
        float inv = 1.0f / l_i[i];
        int row = q0 + ty * 8 + i;
        float4 o;
        o.x = acc[i][0] * inv;
        o.y = acc[i][1] * inv;
        o.z = acc[i][2] * inv;
        o.w = acc[i][3] * inv;
        *(float4*)(O + ((size_t)(b * SS + row)) * DD + h * HD + tx * 4) = o;
    }
}

// ---------------------------------------------------------------------------
// Launch
// ---------------------------------------------------------------------------
extern "C" void kernel_launch(void* const* d_in, const int* in_sizes, int n_in,
                              void* d_out, int out_size)
{
    const float* q  = (const float*)d_in[0];
    const float* k  = (const float*)d_in[1];
    const float* v  = (const float*)d_in[2];
    const float* Wq = (const float*)d_in[3];
    const float* bq = (const float*)d_in[4];
    const float* Wk = (const float*)d_in[5];
    const float* bk = (const float*)d_in[6];
    const float* Wv = (const float*)d_in[7];
    const float* bv = (const float*)d_in[8];
    const float* Wo = (const float*)d_in[9];
    const float* bo = (const float*)d_in[10];
    float* out = (float*)d_out;

    float *qp, *kp, *vp, *att;
    cudaGetSymbolAddress((void**)&qp,  g_qp);
    cudaGetSymbolAddress((void**)&kp,  g_kp);
    cudaGetSymbolAddress((void**)&vp,  g_vp);
    cudaGetSymbolAddress((void**)&att, g_att);

    static bool attr_set = false;
    if (!attr_set) {
        cudaFuncSetAttribute(flash_attn, cudaFuncAttributeMaxDynamicSharedMemorySize,
                             FLASH_SMEM_BYTES);
        attr_set = true;
    }

    dim3 gemm_grid(DD / 128, MM / 128);   // (8, 32)
    sgemm_nt_bias<<<gemm_grid, 256>>>(q, Wq, bq, qp, MM, DD, DD);
    sgemm_nt_bias<<<gemm_grid, 256>>>(k, Wk, bk, kp, MM, DD, DD);
    sgemm_nt_bias<<<gemm_grid, 256>>>(v, Wv, bv, vp, MM, DD, DD);

    dim3 attn_grid(SS / 128, HH, BB);     // (16, 16, 2)
    flash_attn<<<attn_grid, 256, FLASH_SMEM_BYTES>>>(qp, kp, vp, att);

    sgemm_nt_bias<<<gemm_grid, 256>>>(att, Wo, bo, out, MM, DD, DD);
}

// round 3
// speedup vs baseline: 2.5462x; 2.5462x over previous
#include <cuda_runtime.h>
#include <cuda_bf16.h>
#include <cstdint>

// Problem constants
#define BB 2
#define SS 2048
#define DD 1024
#define HH 16
#define HD 64
#define MM (BB * SS)          // 4096 rows
#define ATTN_SCALE 0.125f     // 1/sqrt(64)

// ---------------------------------------------------------------------------
// Scratch (device globals; no runtime allocation allowed)
// ---------------------------------------------------------------------------
__device__ float g_qp[MM * DD];
__device__ float g_kp[MM * DD];
__device__ float g_vp[MM * DD];
__device__ float g_att[MM * DD];

// ---------------------------------------------------------------------------
// tf32 helpers
// ---------------------------------------------------------------------------
__device__ __forceinline__ float tf32r(float x) {
    uint32_t u;
    asm("cvt.rna.tf32.f32 %0, %1;" : "=r"(u) : "f"(x));
    return __uint_as_float(u);
}

__device__ __forceinline__ void mma_tf32(float* d, const uint32_t* a, const uint32_t* b) {
    asm volatile(
        "mma.sync.aligned.m16n8k8.row.col.f32.tf32.tf32.f32 "
        "{%0,%1,%2,%3}, {%4,%5,%6,%7}, {%8,%9}, {%0,%1,%2,%3};\n"
        : "+f"(d[0]), "+f"(d[1]), "+f"(d[2]), "+f"(d[3])
        : "r"(a[0]), "r"(a[1]), "r"(a[2]), "r"(a[3]),
          "r"(b[0]), "r"(b[1]));
}

// ---------------------------------------------------------------------------
// tf32 GEMM (NT): C[M,N] = A[M,K] @ W[N,K]^T + bias[N]
// Block 128x128, BK=16, 256 threads (8 warps: 2m x 4n), warp tile 64x32.
// smem layout: row-major with stride 20 words (bank-conflict-free frag loads:
// address = row*20 + col -> banks (20g + t4) mod 32 is a permutation).
// ---------------------------------------------------------------------------
#define GST 20

__global__ __launch_bounds__(256, 2)
void gemm_tf32_nt_bias(const float* __restrict__ A, const float* __restrict__ W,
                       const float* __restrict__ bias, float* __restrict__ C,
                       int M, int N, int K)
{
    __shared__ float As[128 * GST];
    __shared__ float Ws[128 * GST];

    const int tid  = threadIdx.x;
    const int warp = tid >> 5;
    const int lane = tid & 31;
    const int g  = lane >> 2;
    const int t4 = lane & 3;

    const int wm = (warp & 1) * 64;   // warp m offset in tile
    const int wn = (warp >> 1) * 32;  // warp n offset in tile

    const int m0 = blockIdx.y << 7;
    const int n0 = blockIdx.x << 7;

    float4 a_next[2], w_next[2];
#pragma unroll
    for (int p = 0; p < 2; p++) {
        int idx = tid + p * 256;
        int r = idx >> 2;
        int c = (idx & 3) << 2;
        a_next[p] = *(const float4*)(A + (size_t)(m0 + r) * K + c);
        w_next[p] = *(const float4*)(W + (size_t)(n0 + r) * K + c);
    }

    float acc[4][4][4];
#pragma unroll
    for (int mt = 0; mt < 4; mt++)
#pragma unroll
        for (int nt = 0; nt < 4; nt++)
#pragma unroll
            for (int c = 0; c < 4; c++) acc[mt][nt][c] = 0.f;

    for (int k0 = 0; k0 < K; k0 += 16) {
        __syncthreads();
#pragma unroll
        for (int p = 0; p < 2; p++) {
            int idx = tid + p * 256;
            int r = idx >> 2;
            int c = (idx & 3) << 2;
            float* as = As + r * GST + c;
            as[0] = tf32r(a_next[p].x); as[1] = tf32r(a_next[p].y);
            as[2] = tf32r(a_next[p].z); as[3] = tf32r(a_next[p].w);
            float* ws = Ws + r * GST + c;
            ws[0] = tf32r(w_next[p].x); ws[1] = tf32r(w_next[p].y);
            ws[2] = tf32r(w_next[p].z); ws[3] = tf32r(w_next[p].w);
        }
        __syncthreads();

        if (k0 + 16 < K) {
#pragma unroll
            for (int p = 0; p < 2; p++) {
                int idx = tid + p * 256;
                int r = idx >> 2;
                int c = (idx & 3) << 2;
                a_next[p] = *(const float4*)(A + (size_t)(m0 + r) * K + k0 + 16 + c);
                w_next[p] = *(const float4*)(W + (size_t)(n0 + r) * K + k0 + 16 + c);
            }
        }

#pragma unroll
        for (int ks = 0; ks < 2; ks++) {
            uint32_t af[4][4];
#pragma unroll
            for (int mt = 0; mt < 4; mt++) {
                int rb = wm + mt * 16;
                int cb = ks * 8 + t4;
                af[mt][0] = __float_as_uint(As[(rb + g)     * GST + cb]);
                af[mt][1] = __float_as_uint(As[(rb + g + 8) * GST + cb]);
                af[mt][2] = __float_as_uint(As[(rb + g)     * GST + cb + 4]);
                af[mt][3] = __float_as_uint(As[(rb + g + 8) * GST + cb + 4]);
            }
            uint32_t bf[4][2];
#pragma unroll
            for (int nt = 0; nt < 4; nt++) {
                int rb = wn + nt * 8;
                int cb = ks * 8 + t4;
                bf[nt][0] = __float_as_uint(Ws[(rb + g) * GST + cb]);
                bf[nt][1] = __float_as_uint(Ws[(rb + g) * GST + cb + 4]);
            }
#pragma unroll
            for (int mt = 0; mt < 4; mt++)
#pragma unroll
                for (int nt = 0; nt < 4; nt++)
                    mma_tf32(acc[mt][nt], af[mt], bf[nt]);
        }
    }

    // epilogue
#pragma unroll
    for (int mt = 0; mt < 4; mt++) {
        int row0 = m0 + wm + mt * 16 + g;
#pragma unroll
        for (int nt = 0; nt < 4; nt++) {
            int col = n0 + wn + nt * 8 + t4 * 2;
            float b0 = bias[col], b1 = bias[col + 1];
            float2 v0 = make_float2(acc[mt][nt][0] + b0, acc[mt][nt][1] + b1);
            float2 v1 = make_float2(acc[mt][nt][2] + b0, acc[mt][nt][3] + b1);
            *(float2*)(C + (size_t)row0 * N + col)       = v0;
            *(float2*)(C + (size_t)(row0 + 8) * N + col) = v1;
        }
    }
}

// ---------------------------------------------------------------------------
// Flash attention, tf32 mma, online softmax.
// Grid (S/128, H, B), 256 threads = 8 warps, warp owns 16 query rows.
// smem (stride 68 words: banks (4g + t4) permutation -> conflict-free):
//   QPs[128][68] : Q staged [i][d] (frags to regs once), then reused as P[i][j]
//   Ks [64][68]  : K tile natural [j][d]  (B-frag for QK^T)
//   Vt [64][68]  : V tile transposed [d][j] (B-frag for PV)
// ---------------------------------------------------------------------------
#define AST 68
#define FLASH_SMEM_BYTES ((128 * AST + 64 * AST + 64 * AST) * 4)

__global__ __launch_bounds__(256, 2)
void flash_tf32(const float* __restrict__ Q, const float* __restrict__ K,
                const float* __restrict__ V, float* __restrict__ O)
{
    extern __shared__ float sm[];
    float* QPs = sm;                 // [128][68]
    float* Ks  = QPs + 128 * AST;    // [64][68]
    float* Vt  = Ks  + 64 * AST;     // [64][68]

    const int tid  = threadIdx.x;
    const int warp = tid >> 5;
    const int lane = tid & 31;
    const int g  = lane >> 2;
    const int t4 = lane & 3;
    const int mrow = warp * 16;      // warp's query-row base within tile

    const int q0 = blockIdx.x << 7;
    const int h  = blockIdx.y;
    const int b  = blockIdx.z;

    const float* Qb = Q + ((size_t)(b * SS + q0)) * DD + h * HD;
    const float* Kb = K + ((size_t)b * SS) * DD + h * HD;
    const float* Vb = V + ((size_t)b * SS) * DD + h * HD;

    // stage Q [128][64] scaled + tf32-rounded
#pragma unroll
    for (int p = 0; p < 8; p++) {
        int idx = tid + p * 256;
        int r  = idx >> 4;
        int c4 = (idx & 15) << 2;
        float4 v4 = *(const float4*)(Qb + (size_t)r * DD + c4);
        float4 o4;
        o4.x = tf32r(v4.x * ATTN_SCALE);
        o4.y = tf32r(v4.y * ATTN_SCALE);
        o4.z = tf32r(v4.z * ATTN_SCALE);
        o4.w = tf32r(v4.w * ATTN_SCALE);
        *(float4*)(QPs + r * AST + c4) = o4;
    }
    __syncthreads();

    // Q fragments -> registers (A-frags, 8 k-steps)
    uint32_t qf[8][4];
#pragma unroll
    for (int ks = 0; ks < 8; ks++) {
        int cb = ks * 8 + t4;
        qf[ks][0] = __float_as_uint(QPs[(mrow + g)     * AST + cb]);
        qf[ks][1] = __float_as_uint(QPs[(mrow + g + 8) * AST + cb]);
        qf[ks][2] = __float_as_uint(QPs[(mrow + g)     * AST + cb + 4]);
        qf[ks][3] = __float_as_uint(QPs[(mrow + g + 8) * AST + cb + 4]);
    }

    float o_acc[8][4];
#pragma unroll
    for (int nt = 0; nt < 8; nt++)
#pragma unroll
        for (int c = 0; c < 4; c++) o_acc[nt][c] = 0.f;
    float m0r = -__int_as_float(0x7f800000);
    float m1r = -__int_as_float(0x7f800000);
    float l0r = 0.f, l1r = 0.f;

    for (int j0 = 0; j0 < SS; j0 += 64) {
        __syncthreads();  // Q-frag reads (iter 0) / prev PV reads of Vt done

        // stage K tile natural [j][d]
#pragma unroll
        for (int p = 0; p < 4; p++) {
            int idx = tid + p * 256;
            int r  = idx >> 4;
            int c4 = (idx & 15) << 2;
            float4 v4 = *(const float4*)(Kb + (size_t)(j0 + r) * DD + c4);
            float4 o4;
            o4.x = tf32r(v4.x); o4.y = tf32r(v4.y);
            o4.z = tf32r(v4.z); o4.w = tf32r(v4.w);
            *(float4*)(Ks + r * AST + c4) = o4;
        }
        // stage V tile transposed [d][j]
#pragma unroll
        for (int p = 0; p < 4; p++) {
            int idx = tid + p * 256;
            int d4 = idx >> 6;        // 0..15
            int j  = idx & 63;
            float4 v4 = *(const float4*)(Vb + (size_t)(j0 + j) * DD + (d4 << 2));
            Vt[(d4 * 4 + 0) * AST + j] = tf32r(v4.x);
            Vt[(d4 * 4 + 1) * AST + j] = tf32r(v4.y);
            Vt[(d4 * 4 + 2) * AST + j] = tf32r(v4.z);
            Vt[(d4 * 4 + 3) * AST + j] = tf32r(v4.w);
        }
        __syncthreads();

        // S = Q K^T  (m16 x n64 x k64 per warp)
        float s[8][4];
#pragma unroll
        for (int nt = 0; nt < 8; nt++)
#pragma unroll
            for (int c = 0; c < 4; c++) s[nt][c] = 0.f;

#pragma unroll
        for (int ks = 0; ks < 8; ks++) {
            int cb = ks * 8 + t4;
#pragma unroll
            for (int nt = 0; nt < 8; nt++) {
                uint32_t bf[2];
                bf[0] = __float_as_uint(Ks[(nt * 8 + g) * AST + cb]);
                bf[1] = __float_as_uint(Ks[(nt * 8 + g) * AST + cb + 4]);
                mma_tf32(s[nt], qf[ks], bf);
            }
        }

        // online softmax: rows (mrow+g) and (mrow+g+8)
        float mx0 = s[0][0], mx1 = s[0][2];
#pragma unroll
        for (int nt = 0; nt < 8; nt++) {
            mx0 = fmaxf(mx0, fmaxf(s[nt][0], s[nt][1]));
            mx1 = fmaxf(mx1, fmaxf(s[nt][2], s[nt][3]));
        }
        mx0 = fmaxf(mx0, __shfl_xor_sync(0xffffffffu, mx0, 1));
        mx0 = fmaxf(mx0, __shfl_xor_sync(0xffffffffu, mx0, 2));
        mx1 = fmaxf(mx1, __shfl_xor_sync(0xffffffffu, mx1, 1));
        mx1 = fmaxf(mx1, __shfl_xor_sync(0xffffffffu, mx1, 2));

        float mn0 = fmaxf(m0r, mx0);
        float mn1 = fmaxf(m1r, mx1);
        float corr0 = __expf(m0r - mn0);
        float corr1 = __expf(m1r - mn1);
        m0r = mn0; m1r = mn1;

        float rs0 = 0.f, rs1 = 0.f;
#pragma unroll
        for (int nt = 0; nt < 8; nt++) {
            s[nt][0] = __expf(s[nt][0] - mn0);
            s[nt][1] = __expf(s[nt][1] - mn0);
            s[nt][2] = __expf(s[nt][2] - mn1);
            s[nt][3] = __expf(s[nt][3] - mn1);
            rs0 += s[nt][0] + s[nt][1];
            rs1 += s[nt][2] + s[nt][3];
        }
        rs0 += __shfl_xor_sync(0xffffffffu, rs0, 1);
        rs0 += __shfl_xor_sync(0xffffffffu, rs0, 2);
        rs1 += __shfl_xor_sync(0xffffffffu, rs1, 1);
        rs1 += __shfl_xor_sync(0xffffffffu, rs1, 2);
        l0r = l0r * corr0 + rs0;
        l1r = l1r * corr1 + rs1;

#pragma unroll
        for (int nt = 0; nt < 8; nt++) {
            o_acc[nt][0] *= corr0; o_acc[nt][1] *= corr0;
            o_acc[nt][2] *= corr1; o_acc[nt][3] *= corr1;
        }

        // store P (warp-local region of QPs): P[i][j], stride AST
#pragma unroll
        for (int nt = 0; nt < 8; nt++) {
            int col = nt * 8 + t4 * 2;
            float2 p0 = make_float2(tf32r(s[nt][0]), tf32r(s[nt][1]));
            float2 p1 = make_float2(tf32r(s[nt][2]), tf32r(s[nt][3]));
            *(float2*)(QPs + (mrow + g)     * AST + col) = p0;
            *(float2*)(QPs + (mrow + g + 8) * AST + col) = p1;
        }
        __syncwarp();

        // O += P V   (A = P[i][j], B = Vt[d][j])
#pragma unroll
        for (int ks = 0; ks < 8; ks++) {
            int cb = ks * 8 + t4;
            uint32_t af[4];
            af[0] = __float_as_uint(QPs[(mrow + g)     * AST + cb]);
            af[1] = __float_as_uint(QPs[(mrow + g + 8) * AST + cb]);
            af[2] = __float_as_uint(QPs[(mrow + g)     * AST + cb + 4]);
            af[3] = __float_as_uint(QPs[(mrow + g + 8) * AST + cb + 4]);
#pragma unroll
            for (int nt = 0; nt < 8; nt++) {
                uint32_t bf[2];
                bf[0] = __float_as_uint(Vt[(nt * 8 + g) * AST + cb]);
                bf[1] = __float_as_uint(Vt[(nt * 8 + g) * AST + cb + 4]);
                mma_tf32(o_acc[nt], af, bf);
            }
        }
    }

    // epilogue
    float inv0 = 1.0f / l0r;
    float inv1 = 1.0f / l1r;
    int row0 = q0 + mrow + g;
#pragma unroll
    for (int nt = 0; nt < 8; nt++) {
        int col = h * HD + nt * 8 + t4 * 2;
        float2 v0 = make_float2(o_acc[nt][0] * inv0, o_acc[nt][1] * inv0);
        float2 v1 = make_float2(o_acc[nt][2] * inv1, o_acc[nt][3] * inv1);
        *(float2*)(O + ((size_t)(b * SS + row0)) * DD + col)     = v0;
        *(float2*)(O + ((size_t)(b * SS + row0 + 8)) * DD + col) = v1;
    }
}

// ---------------------------------------------------------------------------
// Launch
// ---------------------------------------------------------------------------
extern "C" void kernel_launch(void* const* d_in, const int* in_sizes, int n_in,
                              void* d_out, int out_size)
{
    const float* q  = (const float*)d_in[0];
    const float* k  = (const float*)d_in[1];
    const float* v  = (const float*)d_in[2];
    const float* Wq = (const float*)d_in[3];
    const float* bq = (const float*)d_in[4];
    const float* Wk = (const float*)d_in[5];
    const float* bk = (const float*)d_in[6];
    const float* Wv = (const float*)d_in[7];
    const float* bv = (const float*)d_in[8];
    const float* Wo = (const float*)d_in[9];
    const float* bo = (const float*)d_in[10];
    float* out = (float*)d_out;

    float *qp, *kp, *vp, *att;
    cudaGetSymbolAddress((void**)&qp,  g_qp);
    cudaGetSymbolAddress((void**)&kp,  g_kp);
    cudaGetSymbolAddress((void**)&vp,  g_vp);
    cudaGetSymbolAddress((void**)&att, g_att);

    cudaFuncSetAttribute(flash_tf32, cudaFuncAttributeMaxDynamicSharedMemorySize,
                         FLASH_SMEM_BYTES);

    dim3 gemm_grid(DD / 128, MM / 128);   // (8, 32)
    gemm_tf32_nt_bias<<<gemm_grid, 256>>>(q, Wq, bq, qp, MM, DD, DD);
    gemm_tf32_nt_bias<<<gemm_grid, 256>>>(k, Wk, bk, kp, MM, DD, DD);
    gemm_tf32_nt_bias<<<gemm_grid, 256>>>(v, Wv, bv, vp, MM, DD, DD);

    dim3 attn_grid(SS / 128, HH, BB);     // (16, 16, 2)
    flash_tf32<<<attn_grid, 256, FLASH_SMEM_BYTES>>>(qp, kp, vp, att);

    gemm_tf32_nt_bias<<<gemm_grid, 256>>>(att, Wo, bo, out, MM, DD, DD);
}

// round 4
// speedup vs baseline: 2.9990x; 1.1779x over previous
#include <cuda_runtime.h>
#include <cstdint>

// Problem constants
#define BB 2
#define SS 2048
#define DD 1024
#define HH 16
#define HD 64
#define MM (BB * SS)          // 4096 rows
#define ATTN_SCALE 0.125f     // 1/sqrt(64)

// ---------------------------------------------------------------------------
// Scratch (device globals; no runtime allocation allowed)
// ---------------------------------------------------------------------------
__device__ float g_qr[MM * DD];    // tf32-rounded q
__device__ float g_kr[MM * DD];
__device__ float g_vr[MM * DD];
__device__ float g_wq[DD * DD];    // tf32-rounded weights
__device__ float g_wk[DD * DD];
__device__ float g_wv[DD * DD];
__device__ float g_wo[DD * DD];
__device__ float g_qp[MM * DD];    // projections (pre-rounded, Q pre-scaled)
__device__ float g_kp[MM * DD];
__device__ float g_vp[MM * DD];
__device__ float g_att[MM * DD];   // attention out (pre-rounded)

// ---------------------------------------------------------------------------
// Helpers
// ---------------------------------------------------------------------------
__device__ __forceinline__ float tf32r(float x) {
    uint32_t u;
    asm("cvt.rna.tf32.f32 %0, %1;" : "=r"(u) : "f"(x));
    return __uint_as_float(u);
}

__device__ __forceinline__ void mma_tf32(float* d, const uint32_t* a, const uint32_t* b) {
    asm volatile(
        "mma.sync.aligned.m16n8k8.row.col.f32.tf32.tf32.f32 "
        "{%0,%1,%2,%3}, {%4,%5,%6,%7}, {%8,%9}, {%0,%1,%2,%3};\n"
        : "+f"(d[0]), "+f"(d[1]), "+f"(d[2]), "+f"(d[3])
        : "r"(a[0]), "r"(a[1]), "r"(a[2]), "r"(a[3]),
          "r"(b[0]), "r"(b[1]));
}

__device__ __forceinline__ void cp_async16(uint32_t smem_dst, const void* gmem_src) {
    asm volatile("cp.async.cg.shared.global [%0], [%1], 16;\n"
                 :: "r"(smem_dst), "l"(gmem_src));
}
__device__ __forceinline__ void cp_commit() {
    asm volatile("cp.async.commit_group;\n");
}
template <int N>
__device__ __forceinline__ void cp_wait() {
    asm volatile("cp.async.wait_group %0;\n" :: "n"(N));
}

// ---------------------------------------------------------------------------
// Elementwise RNA tf32 rounding pass (hoists cvt out of all GEMM mainloops)
// ---------------------------------------------------------------------------
__global__ void round_tf32_kernel(const float4* __restrict__ in,
                                  float4* __restrict__ out, int n4)
{
    int i = blockIdx.x * blockDim.x + threadIdx.x;
    if (i < n4) {
        float4 v = in[i];
        v.x = tf32r(v.x); v.y = tf32r(v.y);
        v.z = tf32r(v.z); v.w = tf32r(v.w);
        out[i] = v;
    }
}

// ---------------------------------------------------------------------------
// Pipelined tf32 GEMM (NT): C[M,N] = A[M,K] @ W[N,K]^T + bias[N]
// Inputs pre-rounded. 128x128 tile, BK=16, 3-stage cp.async, 256 thr, 8 warps.
// MODE: 0 = raw fp32 out, 1 = tf32r(out), 2 = tf32r(out * ATTN_SCALE)
// ---------------------------------------------------------------------------
#define GST 20
#define GSTAGE (128 * GST)
#define GEMM_SMEM_BYTES (3 * GSTAGE * 2 * 4)

template <int MODE>
__global__ __launch_bounds__(256, 2)
void gemm_tf32_pipe(const float* __restrict__ A, const float* __restrict__ W,
                    const float* __restrict__ bias, float* __restrict__ C,
                    int M, int N, int K)
{
    extern __shared__ float smg[];
    float* As = smg;
    float* Ws = smg + 3 * GSTAGE;

    const int tid  = threadIdx.x;
    const int warp = tid >> 5;
    const int lane = tid & 31;
    const int g  = lane >> 2;
    const int t4 = lane & 3;
    const int wm = (warp & 1) * 64;
    const int wn = (warp >> 1) * 32;
    const int m0 = blockIdx.y << 7;
    const int n0 = blockIdx.x << 7;

    const int lr = tid >> 2;          // 0..63 (+64 for second row)
    const int lc = (tid & 3) << 2;    // 0,4,8,12

    const uint32_t as_b = (uint32_t)__cvta_generic_to_shared(As);
    const uint32_t ws_b = (uint32_t)__cvta_generic_to_shared(Ws);

    const int KT = K >> 4;

    auto issue = [&](int kt) {
        int sb = (kt % 3) * GSTAGE;
#pragma unroll
        for (int p = 0; p < 2; p++) {
            int row = lr + p * 64;
            cp_async16(as_b + (uint32_t)(sb + row * GST + lc) * 4u,
                       A + (size_t)(m0 + row) * K + kt * 16 + lc);
            cp_async16(ws_b + (uint32_t)(sb + row * GST + lc) * 4u,
                       W + (size_t)(n0 + row) * K + kt * 16 + lc);
        }
    };

    issue(0); cp_commit();
    issue(1); cp_commit();

    float acc[4][4][4];
#pragma unroll
    for (int mt = 0; mt < 4; mt++)
#pragma unroll
        for (int nt = 0; nt < 4; nt++)
#pragma unroll
            for (int c = 0; c < 4; c++) acc[mt][nt][c] = 0.f;

    for (int kt = 0; kt < KT; kt++) {
        cp_wait<1>();
        __syncthreads();
        if (kt + 2 < KT) issue(kt + 2);
        cp_commit();

        const float* Ab = As + (kt % 3) * GSTAGE;
        const float* Wb = Ws + (kt % 3) * GSTAGE;
#pragma unroll
        for (int ks = 0; ks < 2; ks++) {
            const int cb = ks * 8 + t4;
            uint32_t af[4][4];
#pragma unroll
            for (int mt = 0; mt < 4; mt++) {
                int rb = wm + mt * 16;
                af[mt][0] = __float_as_uint(Ab[(rb + g)     * GST + cb]);
                af[mt][1] = __float_as_uint(Ab[(rb + g + 8) * GST + cb]);
                af[mt][2] = __float_as_uint(Ab[(rb + g)     * GST + cb + 4]);
                af[mt][3] = __float_as_uint(Ab[(rb + g + 8) * GST + cb + 4]);
            }
            uint32_t bf[4][2];
#pragma unroll
            for (int nt = 0; nt < 4; nt++) {
                int rb = wn + nt * 8;
                bf[nt][0] = __float_as_uint(Wb[(rb + g) * GST + cb]);
                bf[nt][1] = __float_as_uint(Wb[(rb + g) * GST + cb + 4]);
            }
#pragma unroll
            for (int mt = 0; mt < 4; mt++)
#pragma unroll
                for (int nt = 0; nt < 4; nt++)
                    mma_tf32(acc[mt][nt], af[mt], bf[nt]);
        }
    }

    // epilogue
#pragma unroll
    for (int mt = 0; mt < 4; mt++) {
        int row0 = m0 + wm + mt * 16 + g;
#pragma unroll
        for (int nt = 0; nt < 4; nt++) {
            int col = n0 + wn + nt * 8 + t4 * 2;
            float b0 = bias[col], b1 = bias[col + 1];
            float v00 = acc[mt][nt][0] + b0, v01 = acc[mt][nt][1] + b1;
            float v10 = acc[mt][nt][2] + b0, v11 = acc[mt][nt][3] + b1;
            if (MODE == 2) {
                v00 *= ATTN_SCALE; v01 *= ATTN_SCALE;
                v10 *= ATTN_SCALE; v11 *= ATTN_SCALE;
            }
            if (MODE >= 1) {
                v00 = tf32r(v00); v01 = tf32r(v01);
                v10 = tf32r(v10); v11 = tf32r(v11);
            }
            *(float2*)(C + (size_t)row0 * N + col)       = make_float2(v00, v01);
            *(float2*)(C + (size_t)(row0 + 8) * N + col) = make_float2(v10, v11);
        }
    }
}

// ---------------------------------------------------------------------------
// Pipelined flash attention, tf32 mma, online softmax.
// Inputs pre-rounded (Q pre-scaled). Output pre-rounded (feeds O-proj).
// Grid (S/128, H, B), 256 threads = 8 warps, warp owns 16 query rows.
// smem: QP[128][68] (Q then P), K[2][64][68] natural, V[2][64][72] natural.
// V natural works as B-frag directly: b[k=j][n=d] = V[j][d]; stride 72 makes
// banks 8*t4+g a permutation -> conflict-free.
// ---------------------------------------------------------------------------
#define QST 68
#define KST 68
#define VST 72
#define FLASH_SMEM_BYTES ((128 * QST + 2 * 64 * KST + 2 * 64 * VST) * 4)

__global__ __launch_bounds__(256, 2)
void flash_tf32_pipe(const float* __restrict__ Q, const float* __restrict__ K,
                     const float* __restrict__ V, float* __restrict__ O)
{
    extern __shared__ float smf[];
    float* QP = smf;                       // [128][68]
    float* Kb = QP + 128 * QST;            // [2][64][68]
    float* Vb = Kb + 2 * 64 * KST;         // [2][64][72]

    const int tid  = threadIdx.x;
    const int warp = tid >> 5;
    const int lane = tid & 31;
    const int g  = lane >> 2;
    const int t4 = lane & 3;
    const int mrow = warp * 16;

    const int q0 = blockIdx.x << 7;
    const int h  = blockIdx.y;
    const int b  = blockIdx.z;

    const float* Qg = Q + ((size_t)(b * SS + q0)) * DD + h * HD;
    const float* Kg = K + ((size_t)b * SS) * DD + h * HD;
    const float* Vg = V + ((size_t)b * SS) * DD + h * HD;

    const uint32_t qp_b = (uint32_t)__cvta_generic_to_shared(QP);
    const uint32_t kb_b = (uint32_t)__cvta_generic_to_shared(Kb);
    const uint32_t vb_b = (uint32_t)__cvta_generic_to_shared(Vb);

    auto issue_kv = [&](int j) {
        int s = j & 1;
#pragma unroll
        for (int p = 0; p < 4; p++) {
            int idx = tid + p * 256;
            int r  = idx >> 4;           // 0..63
            int c  = (idx & 15) << 2;    // 0..60
            cp_async16(kb_b + (uint32_t)(s * 64 * KST + r * KST + c) * 4u,
                       Kg + (size_t)(j * 64 + r) * DD + c);
            cp_async16(vb_b + (uint32_t)(s * 64 * VST + r * VST + c) * 4u,
                       Vg + (size_t)(j * 64 + r) * DD + c);
        }
    };

    // prologue: group0 = Q + K0/V0, group1 = K1/V1
#pragma unroll
    for (int p = 0; p < 8; p++) {
        int idx = tid + p * 256;
        int r  = idx >> 4;               // 0..127
        int c  = (idx & 15) << 2;
        cp_async16(qp_b + (uint32_t)(r * QST + c) * 4u,
                   Qg + (size_t)r * DD + c);
    }
    issue_kv(0);
    cp_commit();
    issue_kv(1);
    cp_commit();

    cp_wait<1>();          // group0 (Q,K0,V0) complete
    __syncthreads();

    // Q fragments -> registers (A-frags, 8 k-steps)
    uint32_t qf[8][4];
#pragma unroll
    for (int ks = 0; ks < 8; ks++) {
        int cb = ks * 8 + t4;
        qf[ks][0] = __float_as_uint(QP[(mrow + g)     * QST + cb]);
        qf[ks][1] = __float_as_uint(QP[(mrow + g + 8) * QST + cb]);
        qf[ks][2] = __float_as_uint(QP[(mrow + g)     * QST + cb + 4]);
        qf[ks][3] = __float_as_uint(QP[(mrow + g + 8) * QST + cb + 4]);
    }

    float o_acc[8][4];
#pragma unroll
    for (int nt = 0; nt < 8; nt++)
#pragma unroll
        for (int c = 0; c < 4; c++) o_acc[nt][c] = 0.f;
    float m0r = -__int_as_float(0x7f800000);
    float m1r = -__int_as_float(0x7f800000);
    float l0r = 0.f, l1r = 0.f;

    for (int j = 0; j < SS / 64; j++) {
        const float* Kt = Kb + (j & 1) * 64 * KST;
        const float* Vt = Vb + (j & 1) * 64 * VST;

        // S = Q K^T  (m16 x n64 x k64 per warp); B[k=d][n=j] = K[j][d]
        float s[8][4];
#pragma unroll
        for (int nt = 0; nt < 8; nt++)
#pragma unroll
            for (int c = 0; c < 4; c++) s[nt][c] = 0.f;

#pragma unroll
        for (int ks = 0; ks < 8; ks++) {
            int cb = ks * 8 + t4;
#pragma unroll
            for (int nt = 0; nt < 8; nt++) {
                uint32_t bf[2];
                bf[0] = __float_as_uint(Kt[(nt * 8 + g) * KST + cb]);
                bf[1] = __float_as_uint(Kt[(nt * 8 + g) * KST + cb + 4]);
                mma_tf32(s[nt], qf[ks], bf);
            }
        }

        // online softmax: rows (mrow+g) and (mrow+g+8)
        float mx0 = s[0][0], mx1 = s[0][2];
#pragma unroll
        for (int nt = 0; nt < 8; nt++) {
            mx0 = fmaxf(mx0, fmaxf(s[nt][0], s[nt][1]));
            mx1 = fmaxf(mx1, fmaxf(s[nt][2], s[nt][3]));
        }
        mx0 = fmaxf(mx0, __shfl_xor_sync(0xffffffffu, mx0, 1));
        mx0 = fmaxf(mx0, __shfl_xor_sync(0xffffffffu, mx0, 2));
        mx1 = fmaxf(mx1, __shfl_xor_sync(0xffffffffu, mx1, 1));
        mx1 = fmaxf(mx1, __shfl_xor_sync(0xffffffffu, mx1, 2));

        float mn0 = fmaxf(m0r, mx0);
        float mn1 = fmaxf(m1r, mx1);
        float corr0 = __expf(m0r - mn0);
        float corr1 = __expf(m1r - mn1);
        m0r = mn0; m1r = mn1;

        float rs0 = 0.f, rs1 = 0.f;
#pragma unroll
        for (int nt = 0; nt < 8; nt++) {
            s[nt][0] = __expf(s[nt][0] - mn0);
            s[nt][1] = __expf(s[nt][1] - mn0);
            s[nt][2] = __expf(s[nt][2] - mn1);
            s[nt][3] = __expf(s[nt][3] - mn1);
            rs0 += s[nt][0] + s[nt][1];
            rs1 += s[nt][2] + s[nt][3];
        }
        rs0 += __shfl_xor_sync(0xffffffffu, rs0, 1);
        rs0 += __shfl_xor_sync(0xffffffffu, rs0, 2);
        rs1 += __shfl_xor_sync(0xffffffffu, rs1, 1);
        rs1 += __shfl_xor_sync(0xffffffffu, rs1, 2);
        l0r = l0r * corr0 + rs0;
        l1r = l1r * corr1 + rs1;

#pragma unroll
        for (int nt = 0; nt < 8; nt++) {
            o_acc[nt][0] *= corr0; o_acc[nt][1] *= corr0;
            o_acc[nt][2] *= corr1; o_acc[nt][3] *= corr1;
        }

        // store P (warp-private rows of QP): P[i][j]
#pragma unroll
        for (int nt = 0; nt < 8; nt++) {
            int col = nt * 8 + t4 * 2;
            *(float2*)(QP + (mrow + g)     * QST + col) =
                make_float2(tf32r(s[nt][0]), tf32r(s[nt][1]));
            *(float2*)(QP + (mrow + g + 8) * QST + col) =
                make_float2(tf32r(s[nt][2]), tf32r(s[nt][3]));
        }
        __syncwarp();

        // O += P V : A = P[i][j], B[k=j][n=d] = V[j][d] (natural layout)
#pragma unroll
        for (int ks = 0; ks < 8; ks++) {
            int cb = ks * 8 + t4;
            uint32_t af[4];
            af[0] = __float_as_uint(QP[(mrow + g)     * QST + cb]);
            af[1] = __float_as_uint(QP[(mrow + g + 8) * QST + cb]);
            af[2] = __float_as_uint(QP[(mrow + g)     * QST + cb + 4]);
            af[3] = __float_as_uint(QP[(mrow + g + 8) * QST + cb + 4]);
#pragma unroll
            for (int nt = 0; nt < 8; nt++) {
                uint32_t bf[2];
                bf[0] = __float_as_uint(Vt[(ks * 8 + t4)     * VST + nt * 8 + g]);
                bf[1] = __float_as_uint(Vt[(ks * 8 + t4 + 4) * VST + nt * 8 + g]);
                mma_tf32(o_acc[nt], af, bf);
            }
        }

        // pipeline turn: free this K/V buffer, refill, arm next
        __syncthreads();
        if (j + 2 < SS / 64) issue_kv(j + 2);
        cp_commit();
        cp_wait<1>();
        __syncthreads();
    }

    // epilogue (pre-rounded for O-projection GEMM)
    float inv0 = 1.0f / l0r;
    float inv1 = 1.0f / l1r;
    int row0 = q0 + mrow + g;
#pragma unroll
    for (int nt = 0; nt < 8; nt++) {
        int col = h * HD + nt * 8 + t4 * 2;
        float2 v0 = make_float2(tf32r(o_acc[nt][0] * inv0), tf32r(o_acc[nt][1] * inv0));
        float2 v1 = make_float2(tf32r(o_acc[nt][2] * inv1), tf32r(o_acc[nt][3] * inv1));
        *(float2*)(O + ((size_t)(b * SS + row0)) * DD + col)     = v0;
        *(float2*)(O + ((size_t)(b * SS + row0 + 8)) * DD + col) = v1;
    }
}

// ---------------------------------------------------------------------------
// Launch
// ---------------------------------------------------------------------------
extern "C" void kernel_launch(void* const* d_in, const int* in_sizes, int n_in,
                              void* d_out, int out_size)
{
    const float* q  = (const float*)d_in[0];
    const float* k  = (const float*)d_in[1];
    const float* v  = (const float*)d_in[2];
    const float* Wq = (const float*)d_in[3];
    const float* bq = (const float*)d_in[4];
    const float* Wk = (const float*)d_in[5];
    const float* bk = (const float*)d_in[6];
    const float* Wv = (const float*)d_in[7];
    const float* bv = (const float*)d_in[8];
    const float* Wo = (const float*)d_in[9];
    const float* bo = (const float*)d_in[10];
    float* out = (float*)d_out;

    float *qr, *kr, *vr, *wq, *wk, *wv, *wo, *qp, *kp, *vp, *att;
    cudaGetSymbolAddress((void**)&qr,  g_qr);
    cudaGetSymbolAddress((void**)&kr,  g_kr);
    cudaGetSymbolAddress((void**)&vr,  g_vr);
    cudaGetSymbolAddress((void**)&wq,  g_wq);
    cudaGetSymbolAddress((void**)&wk,  g_wk);
    cudaGetSymbolAddress((void**)&wv,  g_wv);
    cudaGetSymbolAddress((void**)&wo,  g_wo);
    cudaGetSymbolAddress((void**)&qp,  g_qp);
    cudaGetSymbolAddress((void**)&kp,  g_kp);
    cudaGetSymbolAddress((void**)&vp,  g_vp);
    cudaGetSymbolAddress((void**)&att, g_att);

    cudaFuncSetAttribute(gemm_tf32_pipe<0>, cudaFuncAttributeMaxDynamicSharedMemorySize, GEMM_SMEM_BYTES);
    cudaFuncSetAttribute(gemm_tf32_pipe<1>, cudaFuncAttributeMaxDynamicSharedMemorySize, GEMM_SMEM_BYTES);
    cudaFuncSetAttribute(gemm_tf32_pipe<2>, cudaFuncAttributeMaxDynamicSharedMemorySize, GEMM_SMEM_BYTES);
    cudaFuncSetAttribute(flash_tf32_pipe,  cudaFuncAttributeMaxDynamicSharedMemorySize, FLASH_SMEM_BYTES);

    // 1) RNA-round inputs once (hoists cvt out of all mainloops)
    const int n4a = MM * DD / 4;   // activations
    const int n4w = DD * DD / 4;   // weights
    round_tf32_kernel<<<n4a / 256, 256>>>((const float4*)q,  (float4*)qr, n4a);
    round_tf32_kernel<<<n4a / 256, 256>>>((const float4*)k,  (float4*)kr, n4a);
    round_tf32_kernel<<<n4a / 256, 256>>>((const float4*)v,  (float4*)vr, n4a);
    round_tf32_kernel<<<n4w / 256, 256>>>((const float4*)Wq, (float4*)wq, n4w);
    round_tf32_kernel<<<n4w / 256, 256>>>((const float4*)Wk, (float4*)wk, n4w);
    round_tf32_kernel<<<n4w / 256, 256>>>((const float4*)Wv, (float4*)wv, n4w);
    round_tf32_kernel<<<n4w / 256, 256>>>((const float4*)Wo, (float4*)wo, n4w);

    // 2) Projections (outputs pre-rounded; Q also pre-scaled)
    dim3 gemm_grid(DD / 128, MM / 128);   // (8, 32)
    gemm_tf32_pipe<2><<<gemm_grid, 256, GEMM_SMEM_BYTES>>>(qr, wq, bq, qp, MM, DD, DD);
    gemm_tf32_pipe<1><<<gemm_grid, 256, GEMM_SMEM_BYTES>>>(kr, wk, bk, kp, MM, DD, DD);
    gemm_tf32_pipe<1><<<gemm_grid, 256, GEMM_SMEM_BYTES>>>(vr, wv, bv, vp, MM, DD, DD);

    // 3) Attention
    dim3 attn_grid(SS / 128, HH, BB);     // (16, 16, 2)
    flash_tf32_pipe<<<attn_grid, 256, FLASH_SMEM_BYTES>>>(qp, kp, vp, att);

    // 4) Output projection (raw fp32 result)
    gemm_tf32_pipe<0><<<gemm_grid, 256, GEMM_SMEM_BYTES>>>(att, wo, bo, out, MM, DD, DD);
}

// round 5
// speedup vs baseline: 3.2980x; 1.0997x over previous
#include <cuda_runtime.h>
#include <cstdint>

// Problem constants
#define BB 2
#define SS 2048
#define DD 1024
#define HH 16
#define HD 64
#define MM (BB * SS)          // 4096 rows
#define ATTN_SCALE 0.125f     // 1/sqrt(64)

// ---------------------------------------------------------------------------
// Scratch (device globals; no runtime allocation allowed)
// ---------------------------------------------------------------------------
__device__ float g_qr[MM * DD];    // tf32-rounded q
__device__ float g_kr[MM * DD];
__device__ float g_vr[MM * DD];
__device__ float g_wq[DD * DD];    // tf32-rounded weights
__device__ float g_wk[DD * DD];
__device__ float g_wv[DD * DD];
__device__ float g_wo[DD * DD];
__device__ float g_qp[MM * DD];    // projections (pre-rounded, Q pre-scaled)
__device__ float g_kp[MM * DD];
__device__ float g_vp[MM * DD];
__device__ float g_att[MM * DD];   // attention out (pre-rounded)

// ---------------------------------------------------------------------------
// Helpers
// ---------------------------------------------------------------------------
__device__ __forceinline__ float tf32r(float x) {
    uint32_t u;
    asm("cvt.rna.tf32.f32 %0, %1;" : "=r"(u) : "f"(x));
    return __uint_as_float(u);
}

__device__ __forceinline__ void mma_tf32(float* d, const uint32_t* a, const uint32_t* b) {
    asm volatile(
        "mma.sync.aligned.m16n8k8.row.col.f32.tf32.tf32.f32 "
        "{%0,%1,%2,%3}, {%4,%5,%6,%7}, {%8,%9}, {%0,%1,%2,%3};\n"
        : "+f"(d[0]), "+f"(d[1]), "+f"(d[2]), "+f"(d[3])
        : "r"(a[0]), "r"(a[1]), "r"(a[2]), "r"(a[3]),
          "r"(b[0]), "r"(b[1]));
}

__device__ __forceinline__ void cp_async16(uint32_t smem_dst, const void* gmem_src) {
    asm volatile("cp.async.cg.shared.global [%0], [%1], 16;\n"
                 :: "r"(smem_dst), "l"(gmem_src));
}
__device__ __forceinline__ void cp_commit() {
    asm volatile("cp.async.commit_group;\n");
}
template <int N>
__device__ __forceinline__ void cp_wait() {
    asm volatile("cp.async.wait_group %0;\n" :: "n"(N));
}

// ---------------------------------------------------------------------------
// Single merged RNA-rounding pass for all 7 input tensors.
// Block = 256 thr x 4 float4 = 1024 float4. Activations: 1024 blocks each.
// Weights: 256 blocks each. Grid = 3*1024 + 4*256 = 4096.
// ---------------------------------------------------------------------------
__global__ __launch_bounds__(256)
void round_all_kernel(const float4* __restrict__ q,  const float4* __restrict__ k,
                      const float4* __restrict__ v,  const float4* __restrict__ wq,
                      const float4* __restrict__ wk, const float4* __restrict__ wv,
                      const float4* __restrict__ wo,
                      float4* __restrict__ qr,  float4* __restrict__ kr,
                      float4* __restrict__ vr,  float4* __restrict__ wqr,
                      float4* __restrict__ wkr, float4* __restrict__ wvr,
                      float4* __restrict__ wor)
{
    int bid = blockIdx.x;
    const float4* src; float4* dst; int base;
    if      (bid < 1024) { src = q;  dst = qr;  base = bid;        }
    else if (bid < 2048) { src = k;  dst = kr;  base = bid - 1024; }
    else if (bid < 3072) { src = v;  dst = vr;  base = bid - 2048; }
    else if (bid < 3328) { src = wq; dst = wqr; base = bid - 3072; }
    else if (bid < 3584) { src = wk; dst = wkr; base = bid - 3328; }
    else if (bid < 3840) { src = wv; dst = wvr; base = bid - 3584; }
    else                 { src = wo; dst = wor; base = bid - 3840; }
    int i0 = base * 1024 + threadIdx.x;
#pragma unroll
    for (int u = 0; u < 4; u++) {
        int i = i0 + u * 256;
        float4 t = src[i];
        t.x = tf32r(t.x); t.y = tf32r(t.y);
        t.z = tf32r(t.z); t.w = tf32r(t.w);
        dst[i] = t;
    }
}

// ---------------------------------------------------------------------------
// Pipelined tf32 GEMM body (NT): C = A[M,K] @ W[N,K]^T + bias, M=4096 N=K=1024
// 128x128 tile, BK=16, 3-stage cp.async, 256 thr, 8 warps (warp tile 64x32).
// out = do_round ? tf32r((acc+bias)*scale) : (acc+bias)
// ---------------------------------------------------------------------------
#define GST 20
#define GSTAGE (128 * GST)
#define GEMM_SMEM_BYTES (3 * GSTAGE * 2 * 4)

__device__ __forceinline__
void gemm_body(const float* __restrict__ A, const float* __restrict__ W,
               const float* __restrict__ bias, float* __restrict__ C,
               float scale, bool do_round)
{
    extern __shared__ float smg[];
    float* As = smg;
    float* Ws = smg + 3 * GSTAGE;

    const int tid  = threadIdx.x;
    const int warp = tid >> 5;
    const int lane = tid & 31;
    const int g  = lane >> 2;
    const int t4 = lane & 3;
    const int wm = (warp & 1) * 64;
    const int wn = (warp >> 1) * 32;
    const int m0 = blockIdx.y << 7;
    const int n0 = blockIdx.x << 7;
    const int N = DD, K = DD;

    const int lr = tid >> 2;          // 0..63 (+64 for second row)
    const int lc = (tid & 3) << 2;    // 0,4,8,12

    const uint32_t as_b = (uint32_t)__cvta_generic_to_shared(As);
    const uint32_t ws_b = (uint32_t)__cvta_generic_to_shared(Ws);

    const int KT = K >> 4;

    auto issue = [&](int kt) {
        int sb = (kt % 3) * GSTAGE;
#pragma unroll
        for (int p = 0; p < 2; p++) {
            int row = lr + p * 64;
            cp_async16(as_b + (uint32_t)(sb + row * GST + lc) * 4u,
                       A + (size_t)(m0 + row) * K + kt * 16 + lc);
            cp_async16(ws_b + (uint32_t)(sb + row * GST + lc) * 4u,
                       W + (size_t)(n0 + row) * K + kt * 16 + lc);
        }
    };

    issue(0); cp_commit();
    issue(1); cp_commit();

    float acc[4][4][4];
#pragma unroll
    for (int mt = 0; mt < 4; mt++)
#pragma unroll
        for (int nt = 0; nt < 4; nt++)
#pragma unroll
            for (int c = 0; c < 4; c++) acc[mt][nt][c] = 0.f;

    for (int kt = 0; kt < KT; kt++) {
        cp_wait<1>();
        __syncthreads();
        if (kt + 2 < KT) issue(kt + 2);
        cp_commit();

        const float* Ab = As + (kt % 3) * GSTAGE;
        const float* Wb = Ws + (kt % 3) * GSTAGE;
#pragma unroll
        for (int ks = 0; ks < 2; ks++) {
            const int cb = ks * 8 + t4;
            uint32_t af[4][4];
#pragma unroll
            for (int mt = 0; mt < 4; mt++) {
                int rb = wm + mt * 16;
                af[mt][0] = __float_as_uint(Ab[(rb + g)     * GST + cb]);
                af[mt][1] = __float_as_uint(Ab[(rb + g + 8) * GST + cb]);
                af[mt][2] = __float_as_uint(Ab[(rb + g)     * GST + cb + 4]);
                af[mt][3] = __float_as_uint(Ab[(rb + g + 8) * GST + cb + 4]);
            }
            uint32_t bf[4][2];
#pragma unroll
            for (int nt = 0; nt < 4; nt++) {
                int rb = wn + nt * 8;
                bf[nt][0] = __float_as_uint(Wb[(rb + g) * GST + cb]);
                bf[nt][1] = __float_as_uint(Wb[(rb + g) * GST + cb + 4]);
            }
#pragma unroll
            for (int mt = 0; mt < 4; mt++)
#pragma unroll
                for (int nt = 0; nt < 4; nt++)
                    mma_tf32(acc[mt][nt], af[mt], bf[nt]);
        }
    }

    // epilogue
#pragma unroll
    for (int mt = 0; mt < 4; mt++) {
        int row0 = m0 + wm + mt * 16 + g;
#pragma unroll
        for (int nt = 0; nt < 4; nt++) {
            int col = n0 + wn + nt * 8 + t4 * 2;
            float b0 = bias[col], b1 = bias[col + 1];
            float v00 = acc[mt][nt][0] + b0, v01 = acc[mt][nt][1] + b1;
            float v10 = acc[mt][nt][2] + b0, v11 = acc[mt][nt][3] + b1;
            if (do_round) {
                v00 = tf32r(v00 * scale); v01 = tf32r(v01 * scale);
                v10 = tf32r(v10 * scale); v11 = tf32r(v11 * scale);
            }
            *(float2*)(C + (size_t)row0 * N + col)       = make_float2(v00, v01);
            *(float2*)(C + (size_t)(row0 + 8) * N + col) = make_float2(v10, v11);
        }
    }
}

// Q/K/V projections in one launch: blockIdx.z selects tensor.
__global__ __launch_bounds__(256, 2)
void gemm_qkv(const float* A0, const float* A1, const float* A2,
              const float* W0, const float* W1, const float* W2,
              const float* b0, const float* b1, const float* b2,
              float* C0, float* C1, float* C2)
{
    int z = blockIdx.z;
    const float* A = (z == 0) ? A0 : (z == 1) ? A1 : A2;
    const float* W = (z == 0) ? W0 : (z == 1) ? W1 : W2;
    const float* bi = (z == 0) ? b0 : (z == 1) ? b1 : b2;
    float* C = (z == 0) ? C0 : (z == 1) ? C1 : C2;
    gemm_body(A, W, bi, C, (z == 0) ? ATTN_SCALE : 1.0f, true);
}

// Output projection: raw fp32 result.
__global__ __launch_bounds__(256, 2)
void gemm_o(const float* __restrict__ A, const float* __restrict__ W,
            const float* __restrict__ bias, float* __restrict__ C)
{
    gemm_body(A, W, bias, C, 1.0f, false);
}

// ---------------------------------------------------------------------------
// Flash attention v3: BM=64, 4 warps, 1024 CTAs -> 3 CTAs/SM resident.
// Q staged through K-buffer then register-resident; P never touches smem
// (PV A-frags built from S C-frags via shfl + tf32r -> bit-identical values).
// smem: K[2][64][68], V[2][64][72] = 71,680 B.
// ---------------------------------------------------------------------------
#define KST 68
#define VST 72
#define FLASH_SMEM_BYTES ((2 * 64 * KST + 2 * 64 * VST) * 4)

__global__ __launch_bounds__(128, 3)
void flash_tf32_pipe(const float* __restrict__ Q, const float* __restrict__ K,
                     const float* __restrict__ V, float* __restrict__ O)
{
    extern __shared__ float smf[];
    float* Kb = smf;                       // [2][64][68]
    float* Vb = Kb + 2 * 64 * KST;         // [2][64][72]

    const int tid  = threadIdx.x;
    const int warp = tid >> 5;
    const int lane = tid & 31;
    const int g  = lane >> 2;
    const int t4 = lane & 3;
    const int mrow = warp * 16;

    const int q0 = blockIdx.x << 6;        // 64 q rows per block
    const int h  = blockIdx.y;
    const int b  = blockIdx.z;

    const float* Qg = Q + ((size_t)(b * SS + q0)) * DD + h * HD;
    const float* Kg = K + ((size_t)b * SS) * DD + h * HD;
    const float* Vg = V + ((size_t)b * SS) * DD + h * HD;

    const uint32_t kb_b = (uint32_t)__cvta_generic_to_shared(Kb);
    const uint32_t vb_b = (uint32_t)__cvta_generic_to_shared(Vb);

    auto issue_kv = [&](int j) {
        int s = j & 1;
#pragma unroll
        for (int p = 0; p < 8; p++) {
            int idx = tid + p * 128;
            int r  = idx >> 4;           // 0..63
            int c  = (idx & 15) << 2;    // 0..60
            cp_async16(kb_b + (uint32_t)(s * 64 * KST + r * KST + c) * 4u,
                       Kg + (size_t)(j * 64 + r) * DD + c);
            cp_async16(vb_b + (uint32_t)(s * 64 * VST + r * VST + c) * 4u,
                       Vg + (size_t)(j * 64 + r) * DD + c);
        }
    };

    // Stage Q through K-buffer slot 0, then into registers.
#pragma unroll
    for (int p = 0; p < 8; p++) {
        int idx = tid + p * 128;
        int r  = idx >> 4;               // 0..63
        int c  = (idx & 15) << 2;
        cp_async16(kb_b + (uint32_t)(r * KST + c) * 4u,
                   Qg + (size_t)r * DD + c);
    }
    cp_commit();
    cp_wait<0>();
    __syncthreads();

    uint32_t qf[8][4];
#pragma unroll
    for (int ks = 0; ks < 8; ks++) {
        int cb = ks * 8 + t4;
        qf[ks][0] = __float_as_uint(Kb[(mrow + g)     * KST + cb]);
        qf[ks][1] = __float_as_uint(Kb[(mrow + g + 8) * KST + cb]);
        qf[ks][2] = __float_as_uint(Kb[(mrow + g)     * KST + cb + 4]);
        qf[ks][3] = __float_as_uint(Kb[(mrow + g + 8) * KST + cb + 4]);
    }
    __syncthreads();   // all warps done reading Q before K0 overwrites it

    issue_kv(0); cp_commit();
    issue_kv(1); cp_commit();
    cp_wait<1>();
    __syncthreads();

    float o_acc[8][4];
#pragma unroll
    for (int nt = 0; nt < 8; nt++)
#pragma unroll
        for (int c = 0; c < 4; c++) o_acc[nt][c] = 0.f;
    float m0r = -__int_as_float(0x7f800000);
    float m1r = -__int_as_float(0x7f800000);
    float l0r = 0.f, l1r = 0.f;

    const int srcA = (lane & 28) | (t4 >> 1);
    const int srcB = srcA + 2;
    const bool sel = (t4 & 1) != 0;

    for (int j = 0; j < SS / 64; j++) {
        const float* Kt = Kb + (j & 1) * 64 * KST;
        const float* Vt = Vb + (j & 1) * 64 * VST;

        // S = Q K^T  (m16 x n64 x k64 per warp); B[k=d][n=j] = K[j][d]
        float s[8][4];
#pragma unroll
        for (int nt = 0; nt < 8; nt++)
#pragma unroll
            for (int c = 0; c < 4; c++) s[nt][c] = 0.f;

#pragma unroll
        for (int ks = 0; ks < 8; ks++) {
            int cb = ks * 8 + t4;
#pragma unroll
            for (int nt = 0; nt < 8; nt++) {
                uint32_t bf[2];
                bf[0] = __float_as_uint(Kt[(nt * 8 + g) * KST + cb]);
                bf[1] = __float_as_uint(Kt[(nt * 8 + g) * KST + cb + 4]);
                mma_tf32(s[nt], qf[ks], bf);
            }
        }

        // online softmax: rows (mrow+g) and (mrow+g+8)
        float mx0 = s[0][0], mx1 = s[0][2];
#pragma unroll
        for (int nt = 0; nt < 8; nt++) {
            mx0 = fmaxf(mx0, fmaxf(s[nt][0], s[nt][1]));
            mx1 = fmaxf(mx1, fmaxf(s[nt][2], s[nt][3]));
        }
        mx0 = fmaxf(mx0, __shfl_xor_sync(0xffffffffu, mx0, 1));
        mx0 = fmaxf(mx0, __shfl_xor_sync(0xffffffffu, mx0, 2));
        mx1 = fmaxf(mx1, __shfl_xor_sync(0xffffffffu, mx1, 1));
        mx1 = fmaxf(mx1, __shfl_xor_sync(0xffffffffu, mx1, 2));

        float mn0 = fmaxf(m0r, mx0);
        float mn1 = fmaxf(m1r, mx1);
        float corr0 = __expf(m0r - mn0);
        float corr1 = __expf(m1r - mn1);
        m0r = mn0; m1r = mn1;

        float rs0 = 0.f, rs1 = 0.f;
#pragma unroll
        for (int nt = 0; nt < 8; nt++) {
            s[nt][0] = __expf(s[nt][0] - mn0);
            s[nt][1] = __expf(s[nt][1] - mn0);
            s[nt][2] = __expf(s[nt][2] - mn1);
            s[nt][3] = __expf(s[nt][3] - mn1);
            rs0 += s[nt][0] + s[nt][1];
            rs1 += s[nt][2] + s[nt][3];
        }
        rs0 += __shfl_xor_sync(0xffffffffu, rs0, 1);
        rs0 += __shfl_xor_sync(0xffffffffu, rs0, 2);
        rs1 += __shfl_xor_sync(0xffffffffu, rs1, 1);
        rs1 += __shfl_xor_sync(0xffffffffu, rs1, 2);
        l0r = l0r * corr0 + rs0;
        l1r = l1r * corr1 + rs1;

#pragma unroll
        for (int nt = 0; nt < 8; nt++) {
            o_acc[nt][0] *= corr0; o_acc[nt][1] *= corr0;
            o_acc[nt][2] *= corr1; o_acc[nt][3] *= corr1;
        }

        // O += P V : A-frags for k-step ks come from C-frag s[ks] via shfl.
        // a[0]=P[g][ks*8+t4]   = s[ks][t4&1]   @ lane g*4+(t4>>1)
        // a[1]=P[g+8][ks*8+t4] = s[ks][2+(t4&1)] @ same lane
        // a[2],a[3]: same from lane +2 (cols +4)
#pragma unroll
        for (int ks = 0; ks < 8; ks++) {
            float xA0 = __shfl_sync(0xffffffffu, s[ks][0], srcA);
            float xA1 = __shfl_sync(0xffffffffu, s[ks][1], srcA);
            float xA2 = __shfl_sync(0xffffffffu, s[ks][2], srcA);
            float xA3 = __shfl_sync(0xffffffffu, s[ks][3], srcA);
            float xB0 = __shfl_sync(0xffffffffu, s[ks][0], srcB);
            float xB1 = __shfl_sync(0xffffffffu, s[ks][1], srcB);
            float xB2 = __shfl_sync(0xffffffffu, s[ks][2], srcB);
            float xB3 = __shfl_sync(0xffffffffu, s[ks][3], srcB);
            uint32_t af[4];
            af[0] = __float_as_uint(tf32r(sel ? xA1 : xA0));
            af[1] = __float_as_uint(tf32r(sel ? xA3 : xA2));
            af[2] = __float_as_uint(tf32r(sel ? xB1 : xB0));
            af[3] = __float_as_uint(tf32r(sel ? xB3 : xB2));
#pragma unroll
            for (int nt = 0; nt < 8; nt++) {
                uint32_t bf[2];
                bf[0] = __float_as_uint(Vt[(ks * 8 + t4)     * VST + nt * 8 + g]);
                bf[1] = __float_as_uint(Vt[(ks * 8 + t4 + 4) * VST + nt * 8 + g]);
                mma_tf32(o_acc[nt], af, bf);
            }
        }

        // pipeline turn
        __syncthreads();
        if (j + 2 < SS / 64) issue_kv(j + 2);
        cp_commit();
        cp_wait<1>();
        __syncthreads();
    }

    // epilogue (pre-rounded for O-projection GEMM)
    float inv0 = 1.0f / l0r;
    float inv1 = 1.0f / l1r;
    int row0 = q0 + mrow + g;
#pragma unroll
    for (int nt = 0; nt < 8; nt++) {
        int col = h * HD + nt * 8 + t4 * 2;
        float2 v0 = make_float2(tf32r(o_acc[nt][0] * inv0), tf32r(o_acc[nt][1] * inv0));
        float2 v1 = make_float2(tf32r(o_acc[nt][2] * inv1), tf32r(o_acc[nt][3] * inv1));
        *(float2*)(O + ((size_t)(b * SS + row0)) * DD + col)     = v0;
        *(float2*)(O + ((size_t)(b * SS + row0 + 8)) * DD + col) = v1;
    }
}

// ---------------------------------------------------------------------------
// Launch
// ---------------------------------------------------------------------------
extern "C" void kernel_launch(void* const* d_in, const int* in_sizes, int n_in,
                              void* d_out, int out_size)
{
    const float* q  = (const float*)d_in[0];
    const float* k  = (const float*)d_in[1];
    const float* v  = (const float*)d_in[2];
    const float* Wq = (const float*)d_in[3];
    const float* bq = (const float*)d_in[4];
    const float* Wk = (const float*)d_in[5];
    const float* bk = (const float*)d_in[6];
    const float* Wv = (const float*)d_in[7];
    const float* bv = (const float*)d_in[8];
    const float* Wo = (const float*)d_in[9];
    const float* bo = (const float*)d_in[10];
    float* out = (float*)d_out;

    float *qr, *kr, *vr, *wq, *wk, *wv, *wo, *qp, *kp, *vp, *att;
    cudaGetSymbolAddress((void**)&qr,  g_qr);
    cudaGetSymbolAddress((void**)&kr,  g_kr);
    cudaGetSymbolAddress((void**)&vr,  g_vr);
    cudaGetSymbolAddress((void**)&wq,  g_wq);
    cudaGetSymbolAddress((void**)&wk,  g_wk);
    cudaGetSymbolAddress((void**)&wv,  g_wv);
    cudaGetSymbolAddress((void**)&wo,  g_wo);
    cudaGetSymbolAddress((void**)&qp,  g_qp);
    cudaGetSymbolAddress((void**)&kp,  g_kp);
    cudaGetSymbolAddress((void**)&vp,  g_vp);
    cudaGetSymbolAddress((void**)&att, g_att);

    cudaFuncSetAttribute(gemm_qkv, cudaFuncAttributeMaxDynamicSharedMemorySize, GEMM_SMEM_BYTES);
    cudaFuncSetAttribute(gemm_o,   cudaFuncAttributeMaxDynamicSharedMemorySize, GEMM_SMEM_BYTES);
    cudaFuncSetAttribute(flash_tf32_pipe, cudaFuncAttributeMaxDynamicSharedMemorySize, FLASH_SMEM_BYTES);

    // 1) RNA-round all inputs in one launch
    round_all_kernel<<<4096, 256>>>(
        (const float4*)q,  (const float4*)k,  (const float4*)v,
        (const float4*)Wq, (const float4*)Wk, (const float4*)Wv, (const float4*)Wo,
        (float4*)qr, (float4*)kr, (float4*)vr,
        (float4*)wq, (float4*)wk, (float4*)wv, (float4*)wo);

    // 2) Q/K/V projections in one launch (z selects; Q pre-scaled)
    dim3 qkv_grid(DD / 128, MM / 128, 3);   // (8, 32, 3)
    gemm_qkv<<<qkv_grid, 256, GEMM_SMEM_BYTES>>>(qr, kr, vr, wq, wk, wv,
                                                 bq, bk, bv, qp, kp, vp);

    // 3) Attention (BM=64: 1024 CTAs, 3 CTAs/SM)
    dim3 attn_grid(SS / 64, HH, BB);        // (32, 16, 2)
    flash_tf32_pipe<<<attn_grid, 128, FLASH_SMEM_BYTES>>>(qp, kp, vp, att);

    // 4) Output projection (raw fp32 result)
    dim3 gemm_grid(DD / 128, MM / 128);     // (8, 32)
    gemm_o<<<gemm_grid, 256, GEMM_SMEM_BYTES>>>(att, wo, bo, out);
}

// round 6
// speedup vs baseline: 3.4824x; 1.0559x over previous
#include <cuda_runtime.h>
#include <cstdint>

// Problem constants
#define BB 2
#define SS 2048
#define DD 1024
#define HH 16
#define HD 64
#define MM (BB * SS)          // 4096 rows
#define ATTN_SCALE 0.125f     // 1/sqrt(64)

// ---------------------------------------------------------------------------
// Scratch (device globals; no runtime allocation allowed)
// ---------------------------------------------------------------------------
__device__ float g_qr[MM * DD];    // tf32-rounded q
__device__ float g_kr[MM * DD];
__device__ float g_vr[MM * DD];
__device__ float g_wq[DD * DD];    // tf32-rounded weights
__device__ float g_wk[DD * DD];
__device__ float g_wv[DD * DD];
__device__ float g_wo[DD * DD];
__device__ float g_qp[MM * DD];    // projections (pre-rounded, Q pre-scaled)
__device__ float g_kp[MM * DD];
__device__ float g_vp[MM * DD];
__device__ float g_att[MM * DD];   // attention out (pre-rounded)

// ---------------------------------------------------------------------------
// Helpers
// ---------------------------------------------------------------------------
__device__ __forceinline__ float tf32r(float x) {
    uint32_t u;
    asm("cvt.rna.tf32.f32 %0, %1;" : "=r"(u) : "f"(x));
    return __uint_as_float(u);
}

__device__ __forceinline__ void mma_tf32(float* d, const uint32_t* a, const uint32_t* b) {
    asm volatile(
        "mma.sync.aligned.m16n8k8.row.col.f32.tf32.tf32.f32 "
        "{%0,%1,%2,%3}, {%4,%5,%6,%7}, {%8,%9}, {%0,%1,%2,%3};\n"
        : "+f"(d[0]), "+f"(d[1]), "+f"(d[2]), "+f"(d[3])
        : "r"(a[0]), "r"(a[1]), "r"(a[2]), "r"(a[3]),
          "r"(b[0]), "r"(b[1]));
}

__device__ __forceinline__ void cp_async16(uint32_t smem_dst, const void* gmem_src) {
    asm volatile("cp.async.cg.shared.global [%0], [%1], 16;\n"
                 :: "r"(smem_dst), "l"(gmem_src));
}
__device__ __forceinline__ void cp_commit() {
    asm volatile("cp.async.commit_group;\n");
}
template <int N>
__device__ __forceinline__ void cp_wait() {
    asm volatile("cp.async.wait_group %0;\n" :: "n"(N));
}

// ---------------------------------------------------------------------------
// Single merged RNA-rounding pass for all 7 input tensors.
// ---------------------------------------------------------------------------
__global__ __launch_bounds__(256)
void round_all_kernel(const float4* __restrict__ q,  const float4* __restrict__ k,
                      const float4* __restrict__ v,  const float4* __restrict__ wq,
                      const float4* __restrict__ wk, const float4* __restrict__ wv,
                      const float4* __restrict__ wo,
                      float4* __restrict__ qr,  float4* __restrict__ kr,
                      float4* __restrict__ vr,  float4* __restrict__ wqr,
                      float4* __restrict__ wkr, float4* __restrict__ wvr,
                      float4* __restrict__ wor)
{
    int bid = blockIdx.x;
    const float4* src; float4* dst; int base;
    if      (bid < 1024) { src = q;  dst = qr;  base = bid;        }
    else if (bid < 2048) { src = k;  dst = kr;  base = bid - 1024; }
    else if (bid < 3072) { src = v;  dst = vr;  base = bid - 2048; }
    else if (bid < 3328) { src = wq; dst = wqr; base = bid - 3072; }
    else if (bid < 3584) { src = wk; dst = wkr; base = bid - 3328; }
    else if (bid < 3840) { src = wv; dst = wvr; base = bid - 3584; }
    else                 { src = wo; dst = wor; base = bid - 3840; }
    int i0 = base * 1024 + threadIdx.x;
#pragma unroll
    for (int u = 0; u < 4; u++) {
        int i = i0 + u * 256;
        float4 t = src[i];
        t.x = tf32r(t.x); t.y = tf32r(t.y);
        t.z = tf32r(t.z); t.w = tf32r(t.w);
        dst[i] = t;
    }
}

// ---------------------------------------------------------------------------
// Pipelined tf32 GEMM body (NT): C = A[M,K] @ W[N,K]^T + bias, M=4096 N=K=1024
// 128x128 tile, BK=16, 3-stage cp.async, 256 thr, 8 warps (warp tile 64x32).
// Fragment double-buffering with cross-slab prefetch: every 16-mma block has
// 24 LDS in flight above it (3-stage ring guarantees slab kt+1 resident).
// ---------------------------------------------------------------------------
#define GST 20
#define GSTAGE (128 * GST)
#define GEMM_SMEM_BYTES (3 * GSTAGE * 2 * 4)

__device__ __forceinline__
void load_afbf(const float* __restrict__ Ab, const float* __restrict__ Wb,
               int wm, int wn, int g, int t4, int ks,
               uint32_t af[4][4], uint32_t bf[4][2])
{
    const int cb = ks * 8 + t4;
#pragma unroll
    for (int mt = 0; mt < 4; mt++) {
        int rb = wm + mt * 16;
        af[mt][0] = __float_as_uint(Ab[(rb + g)     * GST + cb]);
        af[mt][1] = __float_as_uint(Ab[(rb + g + 8) * GST + cb]);
        af[mt][2] = __float_as_uint(Ab[(rb + g)     * GST + cb + 4]);
        af[mt][3] = __float_as_uint(Ab[(rb + g + 8) * GST + cb + 4]);
    }
#pragma unroll
    for (int nt = 0; nt < 4; nt++) {
        int rb = wn + nt * 8;
        bf[nt][0] = __float_as_uint(Wb[(rb + g) * GST + cb]);
        bf[nt][1] = __float_as_uint(Wb[(rb + g) * GST + cb + 4]);
    }
}

__device__ __forceinline__
void mma_all(float acc[4][4][4], uint32_t af[4][4], uint32_t bf[4][2])
{
#pragma unroll
    for (int mt = 0; mt < 4; mt++)
#pragma unroll
        for (int nt = 0; nt < 4; nt++)
            mma_tf32(acc[mt][nt], af[mt], bf[nt]);
}

__device__ __forceinline__
void gemm_body(const float* __restrict__ A, const float* __restrict__ W,
               const float* __restrict__ bias, float* __restrict__ C,
               float scale, bool do_round)
{
    extern __shared__ float smg[];
    float* As = smg;
    float* Ws = smg + 3 * GSTAGE;

    const int tid  = threadIdx.x;
    const int warp = tid >> 5;
    const int lane = tid & 31;
    const int g  = lane >> 2;
    const int t4 = lane & 3;
    const int wm = (warp & 1) * 64;
    const int wn = (warp >> 1) * 32;
    const int m0 = blockIdx.y << 7;
    const int n0 = blockIdx.x << 7;
    const int N = DD, K = DD;

    const int lr = tid >> 2;          // 0..63 (+64 for second row)
    const int lc = (tid & 3) << 2;    // 0,4,8,12

    const uint32_t as_b = (uint32_t)__cvta_generic_to_shared(As);
    const uint32_t ws_b = (uint32_t)__cvta_generic_to_shared(Ws);

    const int KT = K >> 4;

    auto issue = [&](int kt) {
        int sb = (kt % 3) * GSTAGE;
#pragma unroll
        for (int p = 0; p < 2; p++) {
            int row = lr + p * 64;
            cp_async16(as_b + (uint32_t)(sb + row * GST + lc) * 4u,
                       A + (size_t)(m0 + row) * K + kt * 16 + lc);
            cp_async16(ws_b + (uint32_t)(sb + row * GST + lc) * 4u,
                       W + (size_t)(n0 + row) * K + kt * 16 + lc);
        }
    };

    issue(0); cp_commit();
    issue(1); cp_commit();

    float acc[4][4][4];
#pragma unroll
    for (int mt = 0; mt < 4; mt++)
#pragma unroll
        for (int nt = 0; nt < 4; nt++)
#pragma unroll
            for (int c = 0; c < 4; c++) acc[mt][nt][c] = 0.f;

    cp_wait<1>();
    __syncthreads();                       // slab 0 visible to all warps

    uint32_t afA[4][4], bfA[4][2], afB[4][4], bfB[4][2];
    load_afbf(As, Ws, wm, wn, g, t4, 0, afA, bfA);   // slab 0, ks0 (buffer 0)

    for (int kt = 0; kt < KT; kt++) {
        // prev-iteration end barrier protects buffer (kt+2)%3 == (kt-1)%3
        if (kt + 2 < KT) issue(kt + 2);
        cp_commit();
        cp_wait<1>();                      // slab kt+1 done (kt+2 in flight)
        __syncthreads();                   // make slab kt+1 visible to all

        const float* Ab  = As + (kt % 3) * GSTAGE;
        const float* Wb  = Ws + (kt % 3) * GSTAGE;
        const float* Abn = As + ((kt + 1) % 3) * GSTAGE;
        const float* Wbn = Ws + ((kt + 1) % 3) * GSTAGE;

        load_afbf(Ab, Wb, wm, wn, g, t4, 1, afB, bfB);     // ks1, this slab
        mma_all(acc, afA, bfA);                            // overlaps B loads
        load_afbf(Abn, Wbn, wm, wn, g, t4, 0, afA, bfA);   // ks0, next slab
        mma_all(acc, afB, bfB);                            // overlaps A loads

        __syncthreads();                   // all reads of buf kt%3 done
    }

    // epilogue
#pragma unroll
    for (int mt = 0; mt < 4; mt++) {
        int row0 = m0 + wm + mt * 16 + g;
#pragma unroll
        for (int nt = 0; nt < 4; nt++) {
            int col = n0 + wn + nt * 8 + t4 * 2;
            float b0 = bias[col], b1 = bias[col + 1];
            float v00 = acc[mt][nt][0] + b0, v01 = acc[mt][nt][1] + b1;
            float v10 = acc[mt][nt][2] + b0, v11 = acc[mt][nt][3] + b1;
            if (do_round) {
                v00 = tf32r(v00 * scale); v01 = tf32r(v01 * scale);
                v10 = tf32r(v10 * scale); v11 = tf32r(v11 * scale);
            }
            *(float2*)(C + (size_t)row0 * N + col)       = make_float2(v00, v01);
            *(float2*)(C + (size_t)(row0 + 8) * N + col) = make_float2(v10, v11);
        }
    }
}

// Q/K/V projections in one launch: blockIdx.z selects tensor.
__global__ __launch_bounds__(256, 2)
void gemm_qkv(const float* A0, const float* A1, const float* A2,
              const float* W0, const float* W1, const float* W2,
              const float* b0, const float* b1, const float* b2,
              float* C0, float* C1, float* C2)
{
    int z = blockIdx.z;
    const float* A = (z == 0) ? A0 : (z == 1) ? A1 : A2;
    const float* W = (z == 0) ? W0 : (z == 1) ? W1 : W2;
    const float* bi = (z == 0) ? b0 : (z == 1) ? b1 : b2;
    float* C = (z == 0) ? C0 : (z == 1) ? C1 : C2;
    gemm_body(A, W, bi, C, (z == 0) ? ATTN_SCALE : 1.0f, true);
}

// Output projection: raw fp32 result.
__global__ __launch_bounds__(256, 2)
void gemm_o(const float* __restrict__ A, const float* __restrict__ W,
            const float* __restrict__ bias, float* __restrict__ C)
{
    gemm_body(A, W, bias, C, 1.0f, false);
}

// ---------------------------------------------------------------------------
// Flash attention v4: BM=64, 4 warps, 1024 CTAs, 3 CTAs/SM.
// Fragment double-buffering inside QK^T and PV loops (LDS/shfl for ks+1
// in flight above mma block for ks). P built from S C-frags via shfl+tf32r.
// smem: K[2][64][68], V[2][64][72] = 71,680 B.
// ---------------------------------------------------------------------------
#define KST 68
#define VST 72
#define FLASH_SMEM_BYTES ((2 * 64 * KST + 2 * 64 * VST) * 4)

__global__ __launch_bounds__(128, 3)
void flash_tf32_pipe(const float* __restrict__ Q, const float* __restrict__ K,
                     const float* __restrict__ V, float* __restrict__ O)
{
    extern __shared__ float smf[];
    float* Kb = smf;                       // [2][64][68]
    float* Vb = Kb + 2 * 64 * KST;         // [2][64][72]

    const int tid  = threadIdx.x;
    const int warp = tid >> 5;
    const int lane = tid & 31;
    const int g  = lane >> 2;
    const int t4 = lane & 3;
    const int mrow = warp * 16;

    const int q0 = blockIdx.x << 6;        // 64 q rows per block
    const int h  = blockIdx.y;
    const int b  = blockIdx.z;

    const float* Qg = Q + ((size_t)(b * SS + q0)) * DD + h * HD;
    const float* Kg = K + ((size_t)b * SS) * DD + h * HD;
    const float* Vg = V + ((size_t)b * SS) * DD + h * HD;

    const uint32_t kb_b = (uint32_t)__cvta_generic_to_shared(Kb);
    const uint32_t vb_b = (uint32_t)__cvta_generic_to_shared(Vb);

    auto issue_kv = [&](int j) {
        int s = j & 1;
#pragma unroll
        for (int p = 0; p < 8; p++) {
            int idx = tid + p * 128;
            int r  = idx >> 4;           // 0..63
            int c  = (idx & 15) << 2;    // 0..60
            cp_async16(kb_b + (uint32_t)(s * 64 * KST + r * KST + c) * 4u,
                       Kg + (size_t)(j * 64 + r) * DD + c);
            cp_async16(vb_b + (uint32_t)(s * 64 * VST + r * VST + c) * 4u,
                       Vg + (size_t)(j * 64 + r) * DD + c);
        }
    };

    // Stage Q through K-buffer slot 0, then into registers.
#pragma unroll
    for (int p = 0; p < 8; p++) {
        int idx = tid + p * 128;
        int r  = idx >> 4;               // 0..63
        int c  = (idx & 15) << 2;
        cp_async16(kb_b + (uint32_t)(r * KST + c) * 4u,
                   Qg + (size_t)r * DD + c);
    }
    cp_commit();
    cp_wait<0>();
    __syncthreads();

    uint32_t qf[8][4];
#pragma unroll
    for (int ks = 0; ks < 8; ks++) {
        int cb = ks * 8 + t4;
        qf[ks][0] = __float_as_uint(Kb[(mrow + g)     * KST + cb]);
        qf[ks][1] = __float_as_uint(Kb[(mrow + g + 8) * KST + cb]);
        qf[ks][2] = __float_as_uint(Kb[(mrow + g)     * KST + cb + 4]);
        qf[ks][3] = __float_as_uint(Kb[(mrow + g + 8) * KST + cb + 4]);
    }
    __syncthreads();   // all warps done reading Q before K0 overwrites it

    issue_kv(0); cp_commit();
    issue_kv(1); cp_commit();
    cp_wait<1>();
    __syncthreads();

    float o_acc[8][4];
#pragma unroll
    for (int nt = 0; nt < 8; nt++)
#pragma unroll
        for (int c = 0; c < 4; c++) o_acc[nt][c] = 0.f;
    float m0r = -__int_as_float(0x7f800000);
    float m1r = -__int_as_float(0x7f800000);
    float l0r = 0.f, l1r = 0.f;

    const int srcA = (lane & 28) | (t4 >> 1);
    const int srcB = srcA + 2;
    const bool sel = (t4 & 1) != 0;

    for (int j = 0; j < SS / 64; j++) {
        const float* Kt = Kb + (j & 1) * 64 * KST;
        const float* Vt = Vb + (j & 1) * 64 * VST;

        // ---- S = Q K^T, K-fragments double-buffered across ks ----
        float s[8][4];
#pragma unroll
        for (int nt = 0; nt < 8; nt++)
#pragma unroll
            for (int c = 0; c < 4; c++) s[nt][c] = 0.f;

        uint32_t kfA[8][2], kfB[8][2];
        {
            const int cb0 = t4;
#pragma unroll
            for (int nt = 0; nt < 8; nt++) {
                kfA[nt][0] = __float_as_uint(Kt[(nt * 8 + g) * KST + cb0]);
                kfA[nt][1] = __float_as_uint(Kt[(nt * 8 + g) * KST + cb0 + 4]);
            }
        }
#pragma unroll
        for (int ks = 0; ks < 8; ks++) {
            uint32_t (*cur)[2] = (ks & 1) ? kfB : kfA;
            uint32_t (*nxt)[2] = (ks & 1) ? kfA : kfB;
            if (ks < 7) {
                const int cb = (ks + 1) * 8 + t4;
#pragma unroll
                for (int nt = 0; nt < 8; nt++) {
                    nxt[nt][0] = __float_as_uint(Kt[(nt * 8 + g) * KST + cb]);
                    nxt[nt][1] = __float_as_uint(Kt[(nt * 8 + g) * KST + cb + 4]);
                }
            }
#pragma unroll
            for (int nt = 0; nt < 8; nt++)
                mma_tf32(s[nt], qf[ks], cur[nt]);
        }

        // ---- online softmax: rows (mrow+g), (mrow+g+8) ----
        float mx0 = s[0][0], mx1 = s[0][2];
#pragma unroll
        for (int nt = 0; nt < 8; nt++) {
            mx0 = fmaxf(mx0, fmaxf(s[nt][0], s[nt][1]));
            mx1 = fmaxf(mx1, fmaxf(s[nt][2], s[nt][3]));
        }
        mx0 = fmaxf(mx0, __shfl_xor_sync(0xffffffffu, mx0, 1));
        mx0 = fmaxf(mx0, __shfl_xor_sync(0xffffffffu, mx0, 2));
        mx1 = fmaxf(mx1, __shfl_xor_sync(0xffffffffu, mx1, 1));
        mx1 = fmaxf(mx1, __shfl_xor_sync(0xffffffffu, mx1, 2));

        float mn0 = fmaxf(m0r, mx0);
        float mn1 = fmaxf(m1r, mx1);
        float corr0 = __expf(m0r - mn0);
        float corr1 = __expf(m1r - mn1);
        m0r = mn0; m1r = mn1;

        float rs0 = 0.f, rs1 = 0.f;
#pragma unroll
        for (int nt = 0; nt < 8; nt++) {
            s[nt][0] = __expf(s[nt][0] - mn0);
            s[nt][1] = __expf(s[nt][1] - mn0);
            s[nt][2] = __expf(s[nt][2] - mn1);
            s[nt][3] = __expf(s[nt][3] - mn1);
            rs0 += s[nt][0] + s[nt][1];
            rs1 += s[nt][2] + s[nt][3];
        }
        rs0 += __shfl_xor_sync(0xffffffffu, rs0, 1);
        rs0 += __shfl_xor_sync(0xffffffffu, rs0, 2);
        rs1 += __shfl_xor_sync(0xffffffffu, rs1, 1);
        rs1 += __shfl_xor_sync(0xffffffffu, rs1, 2);
        l0r = l0r * corr0 + rs0;
        l1r = l1r * corr1 + rs1;

#pragma unroll
        for (int nt = 0; nt < 8; nt++) {
            o_acc[nt][0] *= corr0; o_acc[nt][1] *= corr0;
            o_acc[nt][2] *= corr1; o_acc[nt][3] *= corr1;
        }

        // ---- O += P V, P-frags via shfl, V-frags LDS, both double-buffered
        auto build_af = [&](int ks, uint32_t af[4]) {
            float xA0 = __shfl_sync(0xffffffffu, s[ks][0], srcA);
            float xA1 = __shfl_sync(0xffffffffu, s[ks][1], srcA);
            float xA2 = __shfl_sync(0xffffffffu, s[ks][2], srcA);
            float xA3 = __shfl_sync(0xffffffffu, s[ks][3], srcA);
            float xB0 = __shfl_sync(0xffffffffu, s[ks][0], srcB);
            float xB1 = __shfl_sync(0xffffffffu, s[ks][1], srcB);
            float xB2 = __shfl_sync(0xffffffffu, s[ks][2], srcB);
            float xB3 = __shfl_sync(0xffffffffu, s[ks][3], srcB);
            af[0] = __float_as_uint(tf32r(sel ? xA1 : xA0));
            af[1] = __float_as_uint(tf32r(sel ? xA3 : xA2));
            af[2] = __float_as_uint(tf32r(sel ? xB1 : xB0));
            af[3] = __float_as_uint(tf32r(sel ? xB3 : xB2));
        };
        auto load_vf = [&](int ks, uint32_t vf[8][2]) {
#pragma unroll
            for (int nt = 0; nt < 8; nt++) {
                vf[nt][0] = __float_as_uint(Vt[(ks * 8 + t4)     * VST + nt * 8 + g]);
                vf[nt][1] = __float_as_uint(Vt[(ks * 8 + t4 + 4) * VST + nt * 8 + g]);
            }
        };

        uint32_t pfA[4], pfB[4], vfA[8][2], vfB[8][2];
        build_af(0, pfA);
        load_vf(0, vfA);
#pragma unroll
        for (int ks = 0; ks < 8; ks++) {
            uint32_t* pc = (ks & 1) ? pfB : pfA;
            uint32_t (*vc)[2] = (ks & 1) ? vfB : vfA;
            uint32_t* pn = (ks & 1) ? pfA : pfB;
            uint32_t (*vn)[2] = (ks & 1) ? vfA : vfB;
            if (ks < 7) {
                build_af(ks + 1, pn);
                load_vf(ks + 1, vn);
            }
#pragma unroll
            for (int nt = 0; nt < 8; nt++)
                mma_tf32(o_acc[nt], pc, vc[nt]);
        }

        // pipeline turn
        __syncthreads();
        if (j + 2 < SS / 64) issue_kv(j + 2);
        cp_commit();
        cp_wait<1>();
        __syncthreads();
    }

    // epilogue (pre-rounded for O-projection GEMM)
    float inv0 = 1.0f / l0r;
    float inv1 = 1.0f / l1r;
    int row0 = q0 + mrow + g;
#pragma unroll
    for (int nt = 0; nt < 8; nt++) {
        int col = h * HD + nt * 8 + t4 * 2;
        float2 v0 = make_float2(tf32r(o_acc[nt][0] * inv0), tf32r(o_acc[nt][1] * inv0));
        float2 v1 = make_float2(tf32r(o_acc[nt][2] * inv1), tf32r(o_acc[nt][3] * inv1));
        *(float2*)(O + ((size_t)(b * SS + row0)) * DD + col)     = v0;
        *(float2*)(O + ((size_t)(b * SS + row0 + 8)) * DD + col) = v1;
    }
}

// ---------------------------------------------------------------------------
// Launch
// ---------------------------------------------------------------------------
extern "C" void kernel_launch(void* const* d_in, const int* in_sizes, int n_in,
                              void* d_out, int out_size)
{
    const float* q  = (const float*)d_in[0];
    const float* k  = (const float*)d_in[1];
    const float* v  = (const float*)d_in[2];
    const float* Wq = (const float*)d_in[3];
    const float* bq = (const float*)d_in[4];
    const float* Wk = (const float*)d_in[5];
    const float* bk = (const float*)d_in[6];
    const float* Wv = (const float*)d_in[7];
    const float* bv = (const float*)d_in[8];
    const float* Wo = (const float*)d_in[9];
    const float* bo = (const float*)d_in[10];
    float* out = (float*)d_out;

    float *qr, *kr, *vr, *wq, *wk, *wv, *wo, *qp, *kp, *vp, *att;
    cudaGetSymbolAddress((void**)&qr,  g_qr);
    cudaGetSymbolAddress((void**)&kr,  g_kr);
    cudaGetSymbolAddress((void**)&vr,  g_vr);
    cudaGetSymbolAddress((void**)&wq,  g_wq);
    cudaGetSymbolAddress((void**)&wk,  g_wk);
    cudaGetSymbolAddress((void**)&wv,  g_wv);
    cudaGetSymbolAddress((void**)&wo,  g_wo);
    cudaGetSymbolAddress((void**)&qp,  g_qp);
    cudaGetSymbolAddress((void**)&kp,  g_kp);
    cudaGetSymbolAddress((void**)&vp,  g_vp);
    cudaGetSymbolAddress((void**)&att, g_att);

    cudaFuncSetAttribute(gemm_qkv, cudaFuncAttributeMaxDynamicSharedMemorySize, GEMM_SMEM_BYTES);
    cudaFuncSetAttribute(gemm_o,   cudaFuncAttributeMaxDynamicSharedMemorySize, GEMM_SMEM_BYTES);
    cudaFuncSetAttribute(flash_tf32_pipe, cudaFuncAttributeMaxDynamicSharedMemorySize, FLASH_SMEM_BYTES);

    // 1) RNA-round all inputs in one launch
    round_all_kernel<<<4096, 256>>>(
        (const float4*)q,  (const float4*)k,  (const float4*)v,
        (const float4*)Wq, (const float4*)Wk, (const float4*)Wv, (const float4*)Wo,
        (float4*)qr, (float4*)kr, (float4*)vr,
        (float4*)wq, (float4*)wk, (float4*)wv, (float4*)wo);

    // 2) Q/K/V projections in one launch (z selects; Q pre-scaled)
    dim3 qkv_grid(DD / 128, MM / 128, 3);   // (8, 32, 3)
    gemm_qkv<<<qkv_grid, 256, GEMM_SMEM_BYTES>>>(qr, kr, vr, wq, wk, wv,
                                                 bq, bk, bv, qp, kp, vp);

    // 3) Attention (BM=64: 1024 CTAs, 3 CTAs/SM)
    dim3 attn_grid(SS / 64, HH, BB);        // (32, 16, 2)
    flash_tf32_pipe<<<attn_grid, 128, FLASH_SMEM_BYTES>>>(qp, kp, vp, att);

    // 4) Output projection (raw fp32 result)
    dim3 gemm_grid(DD / 128, MM / 128);     // (8, 32)
    gemm_o<<<gemm_grid, 256, GEMM_SMEM_BYTES>>>(att, wo, bo, out);
}